// round 10
// baseline (speedup 1.0000x reference)
#include <cuda_runtime.h>
#include <cuda_bf16.h>
#include <cstdint>

#define BATCH 16
#define NTOK  4096
#define CDIM  512
#define JDIM  64
#define ROWS  (BATCH*NTOK)   // 65536
#define NCHUNK 256           // 256-row softmax chunks (16 per batch)

// ---------- scratch (device globals; no runtime allocation) ----------
__device__ __nv_bfloat16 g_Wbf[JDIM*CDIM];   // fused w1@m0, [j][c]
__device__ float         g_blog[JDIM];       // b1@m0
__device__ __nv_bfloat16 g_Mbf[CDIM*JDIM];   // fused m1@w2, [c][j]
__device__ float         g_bns[CDIM], g_bnt[CDIM];
// logits, bf16, MMA-fragment order: [row/32 block][lane][32 u32]
__device__ uint32_t      g_logbf[2048*32*32];            // 8 MiB
__device__ float         g_pmax[NCHUNK*JDIM], g_psum[NCHUNK*JDIM];

// ---------- helpers ----------
__device__ __forceinline__ uint32_t packbf(float x, float y) {
    __nv_bfloat162 h = __floats2bfloat162_rn(x, y);
    return *reinterpret_cast<uint32_t*>(&h);
}
__device__ __forceinline__ float rt_bf(float x) {
    return __bfloat162float(__float2bfloat16_rn(x));
}
__device__ __forceinline__ void mma16816(float* c, const uint32_t* a, const uint32_t* b) {
    asm volatile(
        "mma.sync.aligned.m16n8k16.row.col.f32.bf16.bf16.f32 "
        "{%0,%1,%2,%3},{%4,%5,%6,%7},{%8,%9},{%0,%1,%2,%3};"
        : "+f"(c[0]), "+f"(c[1]), "+f"(c[2]), "+f"(c[3])
        : "r"(a[0]), "r"(a[1]), "r"(a[2]), "r"(a[3]), "r"(b[0]), "r"(b[1]));
}

// ---------- K0a: W-fold (+ blog), split-K 4x128, float4 row loads ----------
// blocks [0,512): W[c=blk][j] = sum_q w1[c][q]*m0[q][j] -> g_Wbf[j*512+c]
// block 512:      blog[j] = b1 @ m0[:,j]
__global__ __launch_bounds__(256) void kf_w(const float* __restrict__ w1,
                                            const float* __restrict__ b1,
                                            const float* __restrict__ m0) {
    __shared__ float red[4][64];
    int blk = blockIdx.x, tid = threadIdx.x;
    int ks = tid >> 6, lx = tid & 63;

    const float* row = (blk < 512) ? (w1 + (size_t)blk*CDIM + ks*128)
                                   : (b1 + ks*128);
    const float* m0c = m0 + (size_t)(ks*128)*JDIM + lx;
    const float4* r4 = reinterpret_cast<const float4*>(row);

    float a0=0.f, a1=0.f, a2=0.f, a3=0.f;
    #pragma unroll 8
    for (int q4 = 0; q4 < 32; q4++) {
        float4 w = r4[q4];
        int q = q4 * 4;
        a0 = fmaf(w.x, m0c[(q  )*JDIM], a0);
        a1 = fmaf(w.y, m0c[(q+1)*JDIM], a1);
        a2 = fmaf(w.z, m0c[(q+2)*JDIM], a2);
        a3 = fmaf(w.w, m0c[(q+3)*JDIM], a3);
    }
    red[ks][lx] = (a0 + a1) + (a2 + a3);
    __syncthreads();
    if (tid < 64) {
        float v = (red[0][tid] + red[1][tid]) + (red[2][tid] + red[3][tid]);
        if (blk < 512) g_Wbf[tid*CDIM + blk] = __float2bfloat16_rn(v);
        else           g_blog[tid] = v;
    }
}

// ---------- K0b: M-fold (+ BN), split-K 4x128, float4 row loads ----------
// blocks [0,512): i=blk: j=i>>3, c-chunk=i&7.  M[j][c]=sum_q m1[j][q]w2[q][c]
// block 512:      BN scale/shift
__global__ __launch_bounds__(256) void kf_m(const float* __restrict__ m1,
                                            const float* __restrict__ w2,
                                            const float* __restrict__ gamma,
                                            const float* __restrict__ beta,
                                            const float* __restrict__ bmean,
                                            const float* __restrict__ bvar) {
    __shared__ float red[4][64];
    int blk = blockIdx.x, tid = threadIdx.x;
    int ks = tid >> 6, lx = tid & 63;

    if (blk < 512) {
        int j = blk >> 3, cb = blk & 7;
        int c = cb*64 + lx;
        const float4* r4 = reinterpret_cast<const float4*>(m1 + (size_t)j*CDIM + ks*128);
        const float* w2c = w2 + (size_t)(ks*128)*CDIM + c;
        float a0=0.f, a1=0.f, a2=0.f, a3=0.f;
        #pragma unroll 8
        for (int q4 = 0; q4 < 32; q4++) {
            float4 m = r4[q4];
            int q = q4 * 4;
            a0 = fmaf(m.x, w2c[(q  )*CDIM], a0);
            a1 = fmaf(m.y, w2c[(q+1)*CDIM], a1);
            a2 = fmaf(m.z, w2c[(q+2)*CDIM], a2);
            a3 = fmaf(m.w, w2c[(q+3)*CDIM], a3);
        }
        red[ks][lx] = (a0 + a1) + (a2 + a3);
        __syncthreads();
        if (tid < 64)
            g_Mbf[(cb*64 + tid)*JDIM + j] = __float2bfloat16_rn(
                (red[0][tid] + red[1][tid]) + (red[2][tid] + red[3][tid]));
    } else {
        for (int c = tid; c < CDIM; c += 256) {
            float s = gamma[c] * rsqrtf(bvar[c] + 1e-3f);
            g_bns[c] = s;
            g_bnt[c] = beta[c] - bmean[c] * s;
        }
    }
}

// ---------- K1: logits = inputs @ W + blog; float4 A loads; fused stats ----------
#define SMEM_LOGITS (64*260*4 + 64*4 + 8*64*4 + 64*4)   // 69120 B

__global__ __launch_bounds__(256) void kl_f4(const float* __restrict__ in) {
    extern __shared__ __align__(16) unsigned char dyn_smem[];
    uint32_t* sw32  = reinterpret_cast<uint32_t*>(dyn_smem);          // [64][260] u32
    float*    sblog = reinterpret_cast<float*>(dyn_smem + 64*260*4);  // [64]
    float*    s_red = sblog + 64;                                     // [8][64]
    float*    s_cmx = s_red + 8*64;                                   // [64]

    int tid = threadIdx.x;
    const uint32_t* gw = reinterpret_cast<const uint32_t*>(g_Wbf); // 256 words/row
    for (int i = tid; i < 64*256; i += 256) {
        int j = i >> 8, w = i & 255;
        sw32[j*260 + w] = gw[i];
    }
    if (tid < JDIM) sblog[tid] = g_blog[tid];
    __syncthreads();

    int warp = tid >> 5, lane = tid & 31;
    int qr = lane >> 2, qc = lane & 3;
    int rowbase = blockIdx.x * 256 + warp * 32;

    float acc[2][8][4];
    #pragma unroll
    for (int nt = 0; nt < 8; nt++) {
        float b0 = sblog[nt*8 + qc*2], b1v = sblog[nt*8 + qc*2 + 1];
        #pragma unroll
        for (int s = 0; s < 2; s++) {
            acc[s][nt][0] = b0; acc[s][nt][1] = b1v;
            acc[s][nt][2] = b0; acc[s][nt][3] = b1v;
        }
    }

    const float* abase = in + (size_t)(rowbase + qr) * CDIM + qc*4;

    #pragma unroll 2
    for (int kk = 0; kk < 512; kk += 16) {
        uint32_t a[2][4];
        #pragma unroll
        for (int s = 0; s < 2; s++) {
            const float* p = abase + s*16*CDIM + kk;
            float4 f0 = *reinterpret_cast<const float4*>(p);
            float4 f1 = *reinterpret_cast<const float4*>(p + 8*CDIM);
            a[s][0] = packbf(f0.x, f0.y);   // row qr,   logical k-low
            a[s][1] = packbf(f1.x, f1.y);   // row qr+8, logical k-low
            a[s][2] = packbf(f0.z, f0.w);   // row qr,   logical k-high
            a[s][3] = packbf(f1.z, f1.w);   // row qr+8, logical k-high
        }
        int bofs = (kk >> 1) + qc*2;
        #pragma unroll
        for (int nt = 0; nt < 8; nt++) {
            int n = nt*8 + qr;
            uint32_t b[2];
            b[0] = sw32[n*260 + bofs];       // natural cols 4qc, 4qc+1
            b[1] = sw32[n*260 + bofs + 1];   // natural cols 4qc+2, 4qc+3
            mma16816(acc[0][nt], a[0], b);
            mma16816(acc[1][nt], a[1], b);
        }
    }

    // ---- store logits in bf16 fragment order: 128B contiguous per lane ----
    {
        uint32_t vals[32];
        #pragma unroll
        for (int t = 0; t < 4; t++)
            #pragma unroll
            for (int s = 0; s < 2; s++) {
                int i0 = t*8 + s*4;
                vals[i0+0] = packbf(acc[s][2*t  ][0], acc[s][2*t  ][1]);
                vals[i0+1] = packbf(acc[s][2*t  ][2], acc[s][2*t  ][3]);
                vals[i0+2] = packbf(acc[s][2*t+1][0], acc[s][2*t+1][1]);
                vals[i0+3] = packbf(acc[s][2*t+1][2], acc[s][2*t+1][3]);
            }
        uint4* dst = reinterpret_cast<uint4*>(
            g_logbf + ((size_t)(blockIdx.x*8 + warp))*1024 + lane*32);
        #pragma unroll
        for (int v = 0; v < 8; v++)
            dst[v] = *reinterpret_cast<uint4*>(&vals[v*4]);
    }

    // ---- fused softmax stats over this CTA's 256 rows (bf16-rounded) ----
    #pragma unroll
    for (int nt = 0; nt < 8; nt++) {
        #pragma unroll
        for (int h = 0; h < 2; h++) {
            float v = fmaxf(fmaxf(rt_bf(acc[0][nt][h]), rt_bf(acc[0][nt][h+2])),
                            fmaxf(rt_bf(acc[1][nt][h]), rt_bf(acc[1][nt][h+2])));
            v = fmaxf(v, __shfl_xor_sync(0xffffffffu, v, 4));
            v = fmaxf(v, __shfl_xor_sync(0xffffffffu, v, 8));
            v = fmaxf(v, __shfl_xor_sync(0xffffffffu, v, 16));
            if (lane < 4) s_red[warp*64 + nt*8 + qc*2 + h] = v;
        }
    }
    __syncthreads();
    if (tid < 64) {
        float m = s_red[tid];
        #pragma unroll
        for (int w = 1; w < 8; w++) m = fmaxf(m, s_red[w*64 + tid]);
        s_cmx[tid] = m;
    }
    __syncthreads();
    #pragma unroll
    for (int nt = 0; nt < 8; nt++) {
        #pragma unroll
        for (int h = 0; h < 2; h++) {
            float cm = s_cmx[nt*8 + qc*2 + h];
            float v = __expf(rt_bf(acc[0][nt][h]) - cm) + __expf(rt_bf(acc[0][nt][h+2]) - cm)
                    + __expf(rt_bf(acc[1][nt][h]) - cm) + __expf(rt_bf(acc[1][nt][h+2]) - cm);
            v += __shfl_xor_sync(0xffffffffu, v, 4);
            v += __shfl_xor_sync(0xffffffffu, v, 8);
            v += __shfl_xor_sync(0xffffffffu, v, 16);
            if (lane < 4) s_red[warp*64 + nt*8 + qc*2 + h] = v;
        }
    }
    __syncthreads();
    if (tid < 64) {
        float s = 0.f;
        #pragma unroll
        for (int w = 0; w < 8; w++) s += s_red[w*64 + tid];
        g_pmax[blockIdx.x*JDIM + tid] = s_cmx[tid];
        g_psum[blockIdx.x*JDIM + tid] = s;
    }
}

// ---------- K2: out = relu( BN( (exp(logits-max)*inv) @ M ) + inputs ) ----------
__global__ __launch_bounds__(256) void ko_gemm(const float* __restrict__ in,
                                               float* __restrict__ out) {
    __shared__ __align__(16) __nv_bfloat16 sM[128 * 72];
    __shared__ float s_s[128], s_t[128], s_mx[64], s_iv[64];

    int tid = threadIdx.x;
    int mt = blockIdx.x, nt4 = blockIdx.y;
    int cbase = nt4 * 128;
    int b = mt >> 5;

    uint32_t* sm32 = reinterpret_cast<uint32_t*>(sM);
    const uint32_t* gm = reinterpret_cast<const uint32_t*>(g_Mbf) + cbase*32;
    for (int i = tid; i < 128*32; i += 256) {
        int c = i >> 5, w = i & 31;
        sm32[c*36 + w] = gm[i];
    }
    if (tid < 128) { s_s[tid] = g_bns[cbase + tid]; s_t[tid] = g_bnt[cbase + tid]; }
    if (tid < 64) {
        float pm[16];
        float gmx = -1e30f;
        #pragma unroll
        for (int ch = 0; ch < 16; ch++) {
            pm[ch] = g_pmax[(b*16 + ch)*JDIM + tid];
            gmx = fmaxf(gmx, pm[ch]);
        }
        float Z = 0.f;
        #pragma unroll
        for (int ch = 0; ch < 16; ch++)
            Z += g_psum[(b*16 + ch)*JDIM + tid] * __expf(pm[ch] - gmx);
        s_mx[tid] = gmx;
        s_iv[tid] = 1.f / (Z * (1.f + 1e-9f));
    }
    __syncthreads();

    int warp = tid >> 5, lane = tid & 31;
    int qr = lane >> 2, qc = lane & 3;
    int wm = warp & 3, wn = warp >> 2;
    int rowbase = mt*128 + wm*32;

    float acc[2][8][4];
    #pragma unroll
    for (int s = 0; s < 2; s++)
        #pragma unroll
        for (int nt = 0; nt < 8; nt++)
            #pragma unroll
            for (int r = 0; r < 4; r++) acc[s][nt][r] = 0.f;

    const uint4* lgb = reinterpret_cast<const uint4*>(
        g_logbf + ((size_t)(mt*4 + wm))*1024 + lane*32);

    #pragma unroll
    for (int t = 0; t < 4; t++) {
        int jj = t * 16;
        int j0 = jj + qc*2;
        float mA = s_mx[j0],   mB = s_mx[j0+1], iA = s_iv[j0],   iB = s_iv[j0+1];
        float mC = s_mx[j0+8], mD = s_mx[j0+9], iC = s_iv[j0+8], iD = s_iv[j0+9];
        uint32_t a[2][4];
        #pragma unroll
        for (int s = 0; s < 2; s++) {
            uint4 v = lgb[t*2 + s];
            float2 f0 = __bfloat1622float2(*reinterpret_cast<__nv_bfloat162*>(&v.x));
            float2 f1 = __bfloat1622float2(*reinterpret_cast<__nv_bfloat162*>(&v.y));
            float2 f2 = __bfloat1622float2(*reinterpret_cast<__nv_bfloat162*>(&v.z));
            float2 f3 = __bfloat1622float2(*reinterpret_cast<__nv_bfloat162*>(&v.w));
            a[s][0] = packbf(__expf(f0.x - mA)*iA, __expf(f0.y - mB)*iB);
            a[s][1] = packbf(__expf(f1.x - mA)*iA, __expf(f1.y - mB)*iB);
            a[s][2] = packbf(__expf(f2.x - mC)*iC, __expf(f2.y - mD)*iD);
            a[s][3] = packbf(__expf(f3.x - mC)*iC, __expf(f3.y - mD)*iD);
        }
        int bofs = (jj >> 1) + qc;
        #pragma unroll
        for (int nt = 0; nt < 8; nt++) {
            int cl = wn*64 + nt*8 + qr;
            uint32_t bb[2] = { sm32[cl*36 + bofs], sm32[cl*36 + bofs + 4] };
            mma16816(acc[0][nt], a[0], bb);
            mma16816(acc[1][nt], a[1], bb);
        }
    }

    #pragma unroll
    for (int s = 0; s < 2; s++)
        #pragma unroll
        for (int nt = 0; nt < 8; nt++) {
            int row = rowbase + s*16 + qr;
            int cl  = wn*64 + nt*8 + qc*2;
            int col = cbase + cl;
            float2 r0 = *reinterpret_cast<const float2*>(&in[(size_t)row*CDIM + col]);
            float2 r1 = *reinterpret_cast<const float2*>(&in[(size_t)(row + 8)*CDIM + col]);
            float2 o0, o1;
            o0.x = fmaxf(fmaf(acc[s][nt][0], s_s[cl],   s_t[cl])   + r0.x, 0.f);
            o0.y = fmaxf(fmaf(acc[s][nt][1], s_s[cl+1], s_t[cl+1]) + r0.y, 0.f);
            o1.x = fmaxf(fmaf(acc[s][nt][2], s_s[cl],   s_t[cl])   + r1.x, 0.f);
            o1.y = fmaxf(fmaf(acc[s][nt][3], s_s[cl+1], s_t[cl+1]) + r1.y, 0.f);
            *reinterpret_cast<float2*>(&out[(size_t)row*CDIM + col]) = o0;
            *reinterpret_cast<float2*>(&out[(size_t)(row + 8)*CDIM + col]) = o1;
        }
}

// ---------- launch ----------
extern "C" void kernel_launch(void* const* d_in, const int* in_sizes, int n_in,
                              void* d_out, int out_size) {
    (void)in_sizes; (void)n_in; (void)out_size;
    const float* inputs = (const float*)d_in[0];
    const float* w1     = (const float*)d_in[1];
    const float* b1     = (const float*)d_in[2];
    const float* m0     = (const float*)d_in[3];
    const float* m1     = (const float*)d_in[4];
    const float* w2     = (const float*)d_in[5];
    const float* gamma  = (const float*)d_in[6];
    const float* beta   = (const float*)d_in[7];
    const float* bmean  = (const float*)d_in[8];
    const float* bvar   = (const float*)d_in[9];

    cudaFuncSetAttribute(kl_f4, cudaFuncAttributeMaxDynamicSharedMemorySize,
                         SMEM_LOGITS);

    kf_w<<<513, 256>>>(w1, b1, m0);
    kf_m<<<513, 256>>>(m1, w2, gamma, beta, bmean, bvar);
    kl_f4<<<NCHUNK, 256, SMEM_LOGITS>>>(inputs);
    ko_gemm<<<dim3(ROWS / 128, 4), 256>>>(inputs, (float*)d_out);
}

// round 13
// speedup vs baseline: 1.0635x; 1.0635x over previous
#include <cuda_runtime.h>
#include <cuda_bf16.h>
#include <cstdint>

#define BATCH 16
#define NTOK  4096
#define CDIM  512
#define JDIM  64
#define ROWS  (BATCH*NTOK)   // 65536
#define NCHUNK 256           // 256-row softmax chunks (16 per batch)

// ---------- scratch (device globals; no runtime allocation) ----------
__device__ __nv_bfloat16 g_Wbf[JDIM*CDIM];   // fused w1@m0, [j][c]
__device__ float         g_blog[JDIM];       // b1@m0
__device__ __nv_bfloat16 g_Mbf[CDIM*JDIM];   // fused m1@w2, [c][j]
__device__ float         g_bns[CDIM], g_bnt[CDIM];
// logits (then probabilities), bf16, MMA-fragment order: [row/32 block][lane][32 u32]
__device__ uint32_t      g_logbf[2048*32*32];            // 8 MiB
__device__ float         g_pmax[NCHUNK*JDIM], g_psum[NCHUNK*JDIM];

// ---------- helpers ----------
__device__ __forceinline__ uint32_t packbf(float x, float y) {
    __nv_bfloat162 h = __floats2bfloat162_rn(x, y);
    return *reinterpret_cast<uint32_t*>(&h);
}
__device__ __forceinline__ float2 unpackbf(uint32_t u) {
    return __bfloat1622float2(*reinterpret_cast<__nv_bfloat162*>(&u));
}
__device__ __forceinline__ float rt_bf(float x) {
    return __bfloat162float(__float2bfloat16_rn(x));
}
__device__ __forceinline__ void mma16816(float* c, const uint32_t* a, const uint32_t* b) {
    asm volatile(
        "mma.sync.aligned.m16n8k16.row.col.f32.bf16.bf16.f32 "
        "{%0,%1,%2,%3},{%4,%5,%6,%7},{%8,%9},{%0,%1,%2,%3};"
        : "+f"(c[0]), "+f"(c[1]), "+f"(c[2]), "+f"(c[3])
        : "r"(a[0]), "r"(a[1]), "r"(a[2]), "r"(a[3]), "r"(b[0]), "r"(b[1]));
}

// ---------- K0: fold weights, split-K 4x128, float4 row loads ----------
__global__ __launch_bounds__(256) void kf_fold(const float* __restrict__ w1, const float* __restrict__ b1,
                       const float* __restrict__ m0, const float* __restrict__ m1,
                       const float* __restrict__ w2, const float* __restrict__ gamma,
                       const float* __restrict__ beta, const float* __restrict__ bmean,
                       const float* __restrict__ bvar) {
    __shared__ float red[4][64];
    int blk = blockIdx.x, tid = threadIdx.x;
    int ks = tid >> 6, lx = tid & 63;

    if (blk < 512) {
        const float4* r4 = reinterpret_cast<const float4*>(w1 + (size_t)blk*CDIM + ks*128);
        const float* m0c = m0 + (size_t)(ks*128)*JDIM + lx;
        float a0=0.f, a1=0.f, a2=0.f, a3=0.f;
        #pragma unroll 8
        for (int q4 = 0; q4 < 32; q4++) {
            float4 w = r4[q4];
            int q = q4 * 4;
            a0 = fmaf(w.x, m0c[(q  )*JDIM], a0);
            a1 = fmaf(w.y, m0c[(q+1)*JDIM], a1);
            a2 = fmaf(w.z, m0c[(q+2)*JDIM], a2);
            a3 = fmaf(w.w, m0c[(q+3)*JDIM], a3);
        }
        red[ks][lx] = (a0 + a1) + (a2 + a3);
        __syncthreads();
        if (tid < 64)
            g_Wbf[tid*CDIM + blk] = __float2bfloat16_rn(
                (red[0][tid] + red[1][tid]) + (red[2][tid] + red[3][tid]));
    } else if (blk < 1024) {
        int i = blk - 512;
        int j = i >> 3, cb = i & 7;
        int c = cb*64 + lx;
        const float4* r4 = reinterpret_cast<const float4*>(m1 + (size_t)j*CDIM + ks*128);
        const float* w2c = w2 + (size_t)(ks*128)*CDIM + c;
        float a0=0.f, a1=0.f, a2=0.f, a3=0.f;
        #pragma unroll 8
        for (int q4 = 0; q4 < 32; q4++) {
            float4 m = r4[q4];
            int q = q4 * 4;
            a0 = fmaf(m.x, w2c[(q  )*CDIM], a0);
            a1 = fmaf(m.y, w2c[(q+1)*CDIM], a1);
            a2 = fmaf(m.z, w2c[(q+2)*CDIM], a2);
            a3 = fmaf(m.w, w2c[(q+3)*CDIM], a3);
        }
        red[ks][lx] = (a0 + a1) + (a2 + a3);
        __syncthreads();
        if (tid < 64)
            g_Mbf[(cb*64 + tid)*JDIM + j] = __float2bfloat16_rn(
                (red[0][tid] + red[1][tid]) + (red[2][tid] + red[3][tid]));
    } else if (blk == 1024) {
        for (int c = tid; c < CDIM; c += 256) {
            float s = gamma[c] * rsqrtf(bvar[c] + 1e-3f);
            g_bns[c] = s;
            g_bnt[c] = beta[c] - bmean[c] * s;
        }
    } else {
        const float4* r4 = reinterpret_cast<const float4*>(b1 + ks*128);
        const float* m0c = m0 + (size_t)(ks*128)*JDIM + lx;
        float a0=0.f, a1=0.f, a2=0.f, a3=0.f;
        #pragma unroll 8
        for (int q4 = 0; q4 < 32; q4++) {
            float4 w = r4[q4];
            int q = q4 * 4;
            a0 = fmaf(w.x, m0c[(q  )*JDIM], a0);
            a1 = fmaf(w.y, m0c[(q+1)*JDIM], a1);
            a2 = fmaf(w.z, m0c[(q+2)*JDIM], a2);
            a3 = fmaf(w.w, m0c[(q+3)*JDIM], a3);
        }
        red[ks][lx] = (a0 + a1) + (a2 + a3);
        __syncthreads();
        if (tid < 64)
            g_blog[tid] = (red[0][tid] + red[1][tid]) + (red[2][tid] + red[3][tid]);
    }
}

// ---------- K1: logits = inputs @ W + blog; float4 A loads; fused stats ----------
#define SMEM_LOGITS (64*260*4 + 64*4 + 8*64*4 + 64*4)   // 69120 B

__global__ __launch_bounds__(256) void kl_f4(const float* __restrict__ in) {
    extern __shared__ __align__(16) unsigned char dyn_smem[];
    uint32_t* sw32  = reinterpret_cast<uint32_t*>(dyn_smem);          // [64][260] u32
    float*    sblog = reinterpret_cast<float*>(dyn_smem + 64*260*4);  // [64]
    float*    s_red = sblog + 64;                                     // [8][64]
    float*    s_cmx = s_red + 8*64;                                   // [64]

    int tid = threadIdx.x;
    const uint32_t* gw = reinterpret_cast<const uint32_t*>(g_Wbf); // 256 words/row
    for (int i = tid; i < 64*256; i += 256) {
        int j = i >> 8, w = i & 255;
        sw32[j*260 + w] = gw[i];
    }
    if (tid < JDIM) sblog[tid] = g_blog[tid];
    __syncthreads();

    int warp = tid >> 5, lane = tid & 31;
    int qr = lane >> 2, qc = lane & 3;
    int rowbase = blockIdx.x * 256 + warp * 32;

    float acc[2][8][4];
    #pragma unroll
    for (int nt = 0; nt < 8; nt++) {
        float b0 = sblog[nt*8 + qc*2], b1v = sblog[nt*8 + qc*2 + 1];
        #pragma unroll
        for (int s = 0; s < 2; s++) {
            acc[s][nt][0] = b0; acc[s][nt][1] = b1v;
            acc[s][nt][2] = b0; acc[s][nt][3] = b1v;
        }
    }

    const float* abase = in + (size_t)(rowbase + qr) * CDIM + qc*4;

    #pragma unroll 2
    for (int kk = 0; kk < 512; kk += 16) {
        uint32_t a[2][4];
        #pragma unroll
        for (int s = 0; s < 2; s++) {
            const float* p = abase + s*16*CDIM + kk;
            float4 f0 = *reinterpret_cast<const float4*>(p);
            float4 f1 = *reinterpret_cast<const float4*>(p + 8*CDIM);
            a[s][0] = packbf(f0.x, f0.y);   // row qr,   logical k-low
            a[s][1] = packbf(f1.x, f1.y);   // row qr+8, logical k-low
            a[s][2] = packbf(f0.z, f0.w);   // row qr,   logical k-high
            a[s][3] = packbf(f1.z, f1.w);   // row qr+8, logical k-high
        }
        int bofs = (kk >> 1) + qc*2;
        #pragma unroll
        for (int nt = 0; nt < 8; nt++) {
            int n = nt*8 + qr;
            uint32_t b[2];
            b[0] = sw32[n*260 + bofs];       // natural cols 4qc, 4qc+1
            b[1] = sw32[n*260 + bofs + 1];   // natural cols 4qc+2, 4qc+3
            mma16816(acc[0][nt], a[0], b);
            mma16816(acc[1][nt], a[1], b);
        }
    }

    // ---- store logits in bf16 fragment order: 128B contiguous per lane ----
    {
        uint32_t vals[32];
        #pragma unroll
        for (int t = 0; t < 4; t++)
            #pragma unroll
            for (int s = 0; s < 2; s++) {
                int i0 = t*8 + s*4;
                vals[i0+0] = packbf(acc[s][2*t  ][0], acc[s][2*t  ][1]);
                vals[i0+1] = packbf(acc[s][2*t  ][2], acc[s][2*t  ][3]);
                vals[i0+2] = packbf(acc[s][2*t+1][0], acc[s][2*t+1][1]);
                vals[i0+3] = packbf(acc[s][2*t+1][2], acc[s][2*t+1][3]);
            }
        uint4* dst = reinterpret_cast<uint4*>(
            g_logbf + ((size_t)(blockIdx.x*8 + warp))*1024 + lane*32);
        #pragma unroll
        for (int v = 0; v < 8; v++)
            dst[v] = *reinterpret_cast<uint4*>(&vals[v*4]);
    }

    // ---- fused softmax stats over this CTA's 256 rows (bf16-rounded) ----
    #pragma unroll
    for (int nt = 0; nt < 8; nt++) {
        #pragma unroll
        for (int h = 0; h < 2; h++) {
            float v = fmaxf(fmaxf(rt_bf(acc[0][nt][h]), rt_bf(acc[0][nt][h+2])),
                            fmaxf(rt_bf(acc[1][nt][h]), rt_bf(acc[1][nt][h+2])));
            v = fmaxf(v, __shfl_xor_sync(0xffffffffu, v, 4));
            v = fmaxf(v, __shfl_xor_sync(0xffffffffu, v, 8));
            v = fmaxf(v, __shfl_xor_sync(0xffffffffu, v, 16));
            if (lane < 4) s_red[warp*64 + nt*8 + qc*2 + h] = v;
        }
    }
    __syncthreads();
    if (tid < 64) {
        float m = s_red[tid];
        #pragma unroll
        for (int w = 1; w < 8; w++) m = fmaxf(m, s_red[w*64 + tid]);
        s_cmx[tid] = m;
    }
    __syncthreads();
    #pragma unroll
    for (int nt = 0; nt < 8; nt++) {
        #pragma unroll
        for (int h = 0; h < 2; h++) {
            float cm = s_cmx[nt*8 + qc*2 + h];
            float v = __expf(rt_bf(acc[0][nt][h]) - cm) + __expf(rt_bf(acc[0][nt][h+2]) - cm)
                    + __expf(rt_bf(acc[1][nt][h]) - cm) + __expf(rt_bf(acc[1][nt][h+2]) - cm);
            v += __shfl_xor_sync(0xffffffffu, v, 4);
            v += __shfl_xor_sync(0xffffffffu, v, 8);
            v += __shfl_xor_sync(0xffffffffu, v, 16);
            if (lane < 4) s_red[warp*64 + nt*8 + qc*2 + h] = v;
        }
    }
    __syncthreads();
    if (tid < 64) {
        float s = 0.f;
        #pragma unroll
        for (int w = 0; w < 8; w++) s += s_red[w*64 + tid];
        g_pmax[blockIdx.x*JDIM + tid] = s_cmx[tid];
        g_psum[blockIdx.x*JDIM + tid] = s;
    }
}

// ---------- K1b: logits -> probabilities in place ----------
// grid 256: CTA c handles row-blocks c*8+warp (all in batch b = c>>4).
// t_j = -log(Z_j*(1+1e-9)) - max_j ;  p = exp(l + t_j) == exp(l-max)/Z'
__global__ __launch_bounds__(256) void kp_norm() {
    __shared__ float s_tj[64];
    int tid = threadIdx.x, cta = blockIdx.x;
    int b = cta >> 4;
    if (tid < 64) {
        float pm[16];
        float gmx = -1e30f;
        #pragma unroll
        for (int ch = 0; ch < 16; ch++) {
            pm[ch] = g_pmax[(b*16 + ch)*JDIM + tid];
            gmx = fmaxf(gmx, pm[ch]);
        }
        float Z = 0.f;
        #pragma unroll
        for (int ch = 0; ch < 16; ch++)
            Z += g_psum[(b*16 + ch)*JDIM + tid] * __expf(pm[ch] - gmx);
        s_tj[tid] = -__logf(Z * (1.f + 1e-9f)) - gmx;
    }
    __syncthreads();

    int warp = tid >> 5, lane = tid & 31, qc = lane & 3;
    uint4* p = reinterpret_cast<uint4*>(
        g_logbf + ((size_t)(cta*8 + warp))*1024 + lane*32);

    #pragma unroll
    for (int k = 0; k < 8; k++) {
        int t = k >> 1;
        float tjA = s_tj[16*t + 2*qc],     tjB = s_tj[16*t + 2*qc + 1];
        float tjC = s_tj[16*t + 8 + 2*qc], tjD = s_tj[16*t + 8 + 2*qc + 1];
        uint4 v = p[k];
        float2 f;
        f = unpackbf(v.x); v.x = packbf(__expf(f.x + tjA), __expf(f.y + tjB));
        f = unpackbf(v.y); v.y = packbf(__expf(f.x + tjA), __expf(f.y + tjB));
        f = unpackbf(v.z); v.z = packbf(__expf(f.x + tjC), __expf(f.y + tjD));
        f = unpackbf(v.w); v.w = packbf(__expf(f.x + tjC), __expf(f.y + tjD));
        p[k] = v;
    }
}

// ---------- K2: out = relu( BN( p @ M ) + inputs ), p already bf16 probs ------
__global__ __launch_bounds__(256, 3) void ko_pmm(const float* __restrict__ in,
                                                 float* __restrict__ out) {
    __shared__ __align__(16) __nv_bfloat16 sM[128 * 72];
    __shared__ float s_s[128], s_t[128];

    int tid = threadIdx.x;
    int mt = blockIdx.x, nt4 = blockIdx.y;
    int cbase = nt4 * 128;

    uint32_t* sm32 = reinterpret_cast<uint32_t*>(sM);
    const uint32_t* gm = reinterpret_cast<const uint32_t*>(g_Mbf) + cbase*32;
    for (int i = tid; i < 128*32; i += 256) {
        int c = i >> 5, w = i & 31;
        sm32[c*36 + w] = gm[i];
    }
    if (tid < 128) { s_s[tid] = g_bns[cbase + tid]; s_t[tid] = g_bnt[cbase + tid]; }
    __syncthreads();

    int warp = tid >> 5, lane = tid & 31;
    int qr = lane >> 2, qc = lane & 3;
    int wm = warp & 3, wn = warp >> 2;
    int rowbase = mt*128 + wm*32;

    float acc[2][8][4];
    #pragma unroll
    for (int s = 0; s < 2; s++)
        #pragma unroll
        for (int nt = 0; nt < 8; nt++)
            #pragma unroll
            for (int r = 0; r < 4; r++) acc[s][nt][r] = 0.f;

    const uint4* lgb = reinterpret_cast<const uint4*>(
        g_logbf + ((size_t)(mt*4 + wm))*1024 + lane*32);

    #pragma unroll
    for (int t = 0; t < 4; t++) {
        int jj = t * 16;
        uint32_t a[2][4];
        #pragma unroll
        for (int s = 0; s < 2; s++) {
            uint4 v = lgb[t*2 + s];
            a[s][0] = v.x; a[s][1] = v.y; a[s][2] = v.z; a[s][3] = v.w;
        }
        int bofs = (jj >> 1) + qc;
        #pragma unroll
        for (int nt = 0; nt < 8; nt++) {
            int cl = wn*64 + nt*8 + qr;
            uint32_t bb[2] = { sm32[cl*36 + bofs], sm32[cl*36 + bofs + 4] };
            mma16816(acc[0][nt], a[0], bb);
            mma16816(acc[1][nt], a[1], bb);
        }
    }

    #pragma unroll
    for (int s = 0; s < 2; s++)
        #pragma unroll
        for (int nt = 0; nt < 8; nt++) {
            int row = rowbase + s*16 + qr;
            int cl  = wn*64 + nt*8 + qc*2;
            int col = cbase + cl;
            float2 r0 = *reinterpret_cast<const float2*>(&in[(size_t)row*CDIM + col]);
            float2 r1 = *reinterpret_cast<const float2*>(&in[(size_t)(row + 8)*CDIM + col]);
            float2 o0, o1;
            o0.x = fmaxf(fmaf(acc[s][nt][0], s_s[cl],   s_t[cl])   + r0.x, 0.f);
            o0.y = fmaxf(fmaf(acc[s][nt][1], s_s[cl+1], s_t[cl+1]) + r0.y, 0.f);
            o1.x = fmaxf(fmaf(acc[s][nt][2], s_s[cl],   s_t[cl])   + r1.x, 0.f);
            o1.y = fmaxf(fmaf(acc[s][nt][3], s_s[cl+1], s_t[cl+1]) + r1.y, 0.f);
            *reinterpret_cast<float2*>(&out[(size_t)row*CDIM + col]) = o0;
            *reinterpret_cast<float2*>(&out[(size_t)(row + 8)*CDIM + col]) = o1;
        }
}

// ---------- launch ----------
extern "C" void kernel_launch(void* const* d_in, const int* in_sizes, int n_in,
                              void* d_out, int out_size) {
    (void)in_sizes; (void)n_in; (void)out_size;
    const float* inputs = (const float*)d_in[0];
    const float* w1     = (const float*)d_in[1];
    const float* b1     = (const float*)d_in[2];
    const float* m0     = (const float*)d_in[3];
    const float* m1     = (const float*)d_in[4];
    const float* w2     = (const float*)d_in[5];
    const float* gamma  = (const float*)d_in[6];
    const float* beta   = (const float*)d_in[7];
    const float* bmean  = (const float*)d_in[8];
    const float* bvar   = (const float*)d_in[9];

    cudaFuncSetAttribute(kl_f4, cudaFuncAttributeMaxDynamicSharedMemorySize,
                         SMEM_LOGITS);

    kf_fold<<<1026, 256>>>(w1, b1, m0, m1, w2, gamma, beta, bmean, bvar);
    kl_f4<<<NCHUNK, 256, SMEM_LOGITS>>>(inputs);
    kp_norm<<<256, 256>>>();
    ko_pmm<<<dim3(ROWS / 128, 4), 256>>>(inputs, (float*)d_out);
}

// round 14
// speedup vs baseline: 1.1073x; 1.0412x over previous
#include <cuda_runtime.h>
#include <cuda_bf16.h>
#include <cstdint>

#define BATCH 16
#define NTOK  4096
#define CDIM  512
#define JDIM  64
#define ROWS  (BATCH*NTOK)   // 65536
#define NCHUNK 256           // 256-row softmax chunks (16 per batch)

// ---------- scratch (device globals; no runtime allocation) ----------
__device__ __nv_bfloat16 g_Wbf[JDIM*CDIM];   // fused w1@m0, [j][c]
__device__ float         g_blog[JDIM];       // b1@m0
__device__ __nv_bfloat16 g_Mbf[CDIM*JDIM];   // fused m1@w2, [c][j]
__device__ float         g_bns[CDIM], g_bnt[CDIM];
// logits (then probabilities), bf16, CHUNK-MAJOR fragment order:
//   [row/32 block][chunk 0..7][lane 0..31][4 u32]
// chunk = t*2+s (t = 16-col tile, s = 16-row half); per-lane 4 u32 as before.
__device__ uint32_t      g_logbf[2048*8*32*4];           // 8 MiB
__device__ float         g_pmax[NCHUNK*JDIM], g_psum[NCHUNK*JDIM];

// ---------- helpers ----------
__device__ __forceinline__ uint32_t packbf(float x, float y) {
    __nv_bfloat162 h = __floats2bfloat162_rn(x, y);
    return *reinterpret_cast<uint32_t*>(&h);
}
__device__ __forceinline__ float2 unpackbf(uint32_t u) {
    return __bfloat1622float2(*reinterpret_cast<__nv_bfloat162*>(&u));
}
__device__ __forceinline__ float rt_bf(float x) {
    return __bfloat162float(__float2bfloat16_rn(x));
}
__device__ __forceinline__ void mma16816(float* c, const uint32_t* a, const uint32_t* b) {
    asm volatile(
        "mma.sync.aligned.m16n8k16.row.col.f32.bf16.bf16.f32 "
        "{%0,%1,%2,%3},{%4,%5,%6,%7},{%8,%9},{%0,%1,%2,%3};"
        : "+f"(c[0]), "+f"(c[1]), "+f"(c[2]), "+f"(c[3])
        : "r"(a[0]), "r"(a[1]), "r"(a[2]), "r"(a[3]), "r"(b[0]), "r"(b[1]));
}

// ---------- K0: fold weights, split-K 4x128, float4 row loads ----------
__global__ __launch_bounds__(256) void kf_fold(const float* __restrict__ w1, const float* __restrict__ b1,
                       const float* __restrict__ m0, const float* __restrict__ m1,
                       const float* __restrict__ w2, const float* __restrict__ gamma,
                       const float* __restrict__ beta, const float* __restrict__ bmean,
                       const float* __restrict__ bvar) {
    __shared__ float red[4][64];
    int blk = blockIdx.x, tid = threadIdx.x;
    int ks = tid >> 6, lx = tid & 63;

    if (blk < 512) {
        const float4* r4 = reinterpret_cast<const float4*>(w1 + (size_t)blk*CDIM + ks*128);
        const float* m0c = m0 + (size_t)(ks*128)*JDIM + lx;
        float a0=0.f, a1=0.f, a2=0.f, a3=0.f;
        #pragma unroll 8
        for (int q4 = 0; q4 < 32; q4++) {
            float4 w = r4[q4];
            int q = q4 * 4;
            a0 = fmaf(w.x, m0c[(q  )*JDIM], a0);
            a1 = fmaf(w.y, m0c[(q+1)*JDIM], a1);
            a2 = fmaf(w.z, m0c[(q+2)*JDIM], a2);
            a3 = fmaf(w.w, m0c[(q+3)*JDIM], a3);
        }
        red[ks][lx] = (a0 + a1) + (a2 + a3);
        __syncthreads();
        if (tid < 64)
            g_Wbf[tid*CDIM + blk] = __float2bfloat16_rn(
                (red[0][tid] + red[1][tid]) + (red[2][tid] + red[3][tid]));
    } else if (blk < 1024) {
        int i = blk - 512;
        int j = i >> 3, cb = i & 7;
        int c = cb*64 + lx;
        const float4* r4 = reinterpret_cast<const float4*>(m1 + (size_t)j*CDIM + ks*128);
        const float* w2c = w2 + (size_t)(ks*128)*CDIM + c;
        float a0=0.f, a1=0.f, a2=0.f, a3=0.f;
        #pragma unroll 8
        for (int q4 = 0; q4 < 32; q4++) {
            float4 m = r4[q4];
            int q = q4 * 4;
            a0 = fmaf(m.x, w2c[(q  )*CDIM], a0);
            a1 = fmaf(m.y, w2c[(q+1)*CDIM], a1);
            a2 = fmaf(m.z, w2c[(q+2)*CDIM], a2);
            a3 = fmaf(m.w, w2c[(q+3)*CDIM], a3);
        }
        red[ks][lx] = (a0 + a1) + (a2 + a3);
        __syncthreads();
        if (tid < 64)
            g_Mbf[(cb*64 + tid)*JDIM + j] = __float2bfloat16_rn(
                (red[0][tid] + red[1][tid]) + (red[2][tid] + red[3][tid]));
    } else if (blk == 1024) {
        for (int c = tid; c < CDIM; c += 256) {
            float s = gamma[c] * rsqrtf(bvar[c] + 1e-3f);
            g_bns[c] = s;
            g_bnt[c] = beta[c] - bmean[c] * s;
        }
    } else {
        const float4* r4 = reinterpret_cast<const float4*>(b1 + ks*128);
        const float* m0c = m0 + (size_t)(ks*128)*JDIM + lx;
        float a0=0.f, a1=0.f, a2=0.f, a3=0.f;
        #pragma unroll 8
        for (int q4 = 0; q4 < 32; q4++) {
            float4 w = r4[q4];
            int q = q4 * 4;
            a0 = fmaf(w.x, m0c[(q  )*JDIM], a0);
            a1 = fmaf(w.y, m0c[(q+1)*JDIM], a1);
            a2 = fmaf(w.z, m0c[(q+2)*JDIM], a2);
            a3 = fmaf(w.w, m0c[(q+3)*JDIM], a3);
        }
        red[ks][lx] = (a0 + a1) + (a2 + a3);
        __syncthreads();
        if (tid < 64)
            g_blog[tid] = (red[0][tid] + red[1][tid]) + (red[2][tid] + red[3][tid]);
    }
}

// ---------- K1: logits = inputs @ W + blog; float4 A loads; fused stats ----------
#define SMEM_LOGITS (64*260*4 + 64*4 + 8*64*4 + 64*4)   // 69120 B

__global__ __launch_bounds__(256) void kl_f4(const float* __restrict__ in) {
    extern __shared__ __align__(16) unsigned char dyn_smem[];
    uint32_t* sw32  = reinterpret_cast<uint32_t*>(dyn_smem);          // [64][260] u32
    float*    sblog = reinterpret_cast<float*>(dyn_smem + 64*260*4);  // [64]
    float*    s_red = sblog + 64;                                     // [8][64]
    float*    s_cmx = s_red + 8*64;                                   // [64]

    int tid = threadIdx.x;
    const uint32_t* gw = reinterpret_cast<const uint32_t*>(g_Wbf); // 256 words/row
    for (int i = tid; i < 64*256; i += 256) {
        int j = i >> 8, w = i & 255;
        sw32[j*260 + w] = gw[i];
    }
    if (tid < JDIM) sblog[tid] = g_blog[tid];
    __syncthreads();

    int warp = tid >> 5, lane = tid & 31;
    int qr = lane >> 2, qc = lane & 3;
    int rowbase = blockIdx.x * 256 + warp * 32;

    float acc[2][8][4];
    #pragma unroll
    for (int nt = 0; nt < 8; nt++) {
        float b0 = sblog[nt*8 + qc*2], b1v = sblog[nt*8 + qc*2 + 1];
        #pragma unroll
        for (int s = 0; s < 2; s++) {
            acc[s][nt][0] = b0; acc[s][nt][1] = b1v;
            acc[s][nt][2] = b0; acc[s][nt][3] = b1v;
        }
    }

    const float* abase = in + (size_t)(rowbase + qr) * CDIM + qc*4;

    #pragma unroll 2
    for (int kk = 0; kk < 512; kk += 16) {
        uint32_t a[2][4];
        #pragma unroll
        for (int s = 0; s < 2; s++) {
            const float* p = abase + s*16*CDIM + kk;
            float4 f0 = *reinterpret_cast<const float4*>(p);
            float4 f1 = *reinterpret_cast<const float4*>(p + 8*CDIM);
            a[s][0] = packbf(f0.x, f0.y);   // row qr,   logical k-low
            a[s][1] = packbf(f1.x, f1.y);   // row qr+8, logical k-low
            a[s][2] = packbf(f0.z, f0.w);   // row qr,   logical k-high
            a[s][3] = packbf(f1.z, f1.w);   // row qr+8, logical k-high
        }
        int bofs = (kk >> 1) + qc*2;
        #pragma unroll
        for (int nt = 0; nt < 8; nt++) {
            int n = nt*8 + qr;
            uint32_t b[2];
            b[0] = sw32[n*260 + bofs];       // natural cols 4qc, 4qc+1
            b[1] = sw32[n*260 + bofs + 1];   // natural cols 4qc+2, 4qc+3
            mma16816(acc[0][nt], a[0], b);
            mma16816(acc[1][nt], a[1], b);
        }
    }

    // ---- store logits, chunk-major: each STG is 512B contiguous per warp ----
    {
        uint32_t* dstbase = g_logbf + ((size_t)(blockIdx.x*8 + warp))*1024 + lane*4;
        #pragma unroll
        for (int t = 0; t < 4; t++)
            #pragma unroll
            for (int s = 0; s < 2; s++) {
                uint4 v;
                v.x = packbf(acc[s][2*t  ][0], acc[s][2*t  ][1]);
                v.y = packbf(acc[s][2*t  ][2], acc[s][2*t  ][3]);
                v.z = packbf(acc[s][2*t+1][0], acc[s][2*t+1][1]);
                v.w = packbf(acc[s][2*t+1][2], acc[s][2*t+1][3]);
                *reinterpret_cast<uint4*>(dstbase + (t*2 + s)*128) = v;
            }
    }

    // ---- fused softmax stats over this CTA's 256 rows (bf16-rounded) ----
    #pragma unroll
    for (int nt = 0; nt < 8; nt++) {
        #pragma unroll
        for (int h = 0; h < 2; h++) {
            float v = fmaxf(fmaxf(rt_bf(acc[0][nt][h]), rt_bf(acc[0][nt][h+2])),
                            fmaxf(rt_bf(acc[1][nt][h]), rt_bf(acc[1][nt][h+2])));
            v = fmaxf(v, __shfl_xor_sync(0xffffffffu, v, 4));
            v = fmaxf(v, __shfl_xor_sync(0xffffffffu, v, 8));
            v = fmaxf(v, __shfl_xor_sync(0xffffffffu, v, 16));
            if (lane < 4) s_red[warp*64 + nt*8 + qc*2 + h] = v;
        }
    }
    __syncthreads();
    if (tid < 64) {
        float m = s_red[tid];
        #pragma unroll
        for (int w = 1; w < 8; w++) m = fmaxf(m, s_red[w*64 + tid]);
        s_cmx[tid] = m;
    }
    __syncthreads();
    #pragma unroll
    for (int nt = 0; nt < 8; nt++) {
        #pragma unroll
        for (int h = 0; h < 2; h++) {
            float cm = s_cmx[nt*8 + qc*2 + h];
            float v = __expf(rt_bf(acc[0][nt][h]) - cm) + __expf(rt_bf(acc[0][nt][h+2]) - cm)
                    + __expf(rt_bf(acc[1][nt][h]) - cm) + __expf(rt_bf(acc[1][nt][h+2]) - cm);
            v += __shfl_xor_sync(0xffffffffu, v, 4);
            v += __shfl_xor_sync(0xffffffffu, v, 8);
            v += __shfl_xor_sync(0xffffffffu, v, 16);
            if (lane < 4) s_red[warp*64 + nt*8 + qc*2 + h] = v;
        }
    }
    __syncthreads();
    if (tid < 64) {
        float s = 0.f;
        #pragma unroll
        for (int w = 0; w < 8; w++) s += s_red[w*64 + tid];
        g_pmax[blockIdx.x*JDIM + tid] = s_cmx[tid];
        g_psum[blockIdx.x*JDIM + tid] = s;
    }
}

// ---------- K1b: logits -> probabilities in place (chunk-major) ----------
// t_j = -log(Z_j*(1+1e-9)) - max_j ;  p = exp(l + t_j)
__global__ __launch_bounds__(256) void kp_norm() {
    __shared__ float s_tj[64];
    int tid = threadIdx.x, cta = blockIdx.x;
    int b = cta >> 4;
    if (tid < 64) {
        float pm[16];
        float gmx = -1e30f;
        #pragma unroll
        for (int ch = 0; ch < 16; ch++) {
            pm[ch] = g_pmax[(b*16 + ch)*JDIM + tid];
            gmx = fmaxf(gmx, pm[ch]);
        }
        float Z = 0.f;
        #pragma unroll
        for (int ch = 0; ch < 16; ch++)
            Z += g_psum[(b*16 + ch)*JDIM + tid] * __expf(pm[ch] - gmx);
        s_tj[tid] = -__logf(Z * (1.f + 1e-9f)) - gmx;
    }
    __syncthreads();

    int warp = tid >> 5, lane = tid & 31, qc = lane & 3;
    uint32_t* pb = g_logbf + ((size_t)(cta*8 + warp))*1024 + lane*4;

    #pragma unroll
    for (int k = 0; k < 8; k++) {
        int t = k >> 1;
        float tjA = s_tj[16*t + 2*qc],     tjB = s_tj[16*t + 2*qc + 1];
        float tjC = s_tj[16*t + 8 + 2*qc], tjD = s_tj[16*t + 8 + 2*qc + 1];
        uint4 v = *reinterpret_cast<const uint4*>(pb + k*128);
        float2 f;
        f = unpackbf(v.x); v.x = packbf(__expf(f.x + tjA), __expf(f.y + tjB));
        f = unpackbf(v.y); v.y = packbf(__expf(f.x + tjA), __expf(f.y + tjB));
        f = unpackbf(v.z); v.z = packbf(__expf(f.x + tjC), __expf(f.y + tjD));
        f = unpackbf(v.w); v.w = packbf(__expf(f.x + tjC), __expf(f.y + tjD));
        *reinterpret_cast<uint4*>(pb + k*128) = v;
    }
}

// ---------- K2: out = relu( BN( p @ M ) + inputs ), float4 shuffle epilogue ----
__global__ __launch_bounds__(256, 3) void ko_pmm(const float* __restrict__ in,
                                                 float* __restrict__ out) {
    __shared__ __align__(16) __nv_bfloat16 sM[128 * 72];
    __shared__ __align__(16) float s_s[128];
    __shared__ __align__(16) float s_t[128];

    int tid = threadIdx.x;
    int mt = blockIdx.x, nt4 = blockIdx.y;
    int cbase = nt4 * 128;

    uint32_t* sm32 = reinterpret_cast<uint32_t*>(sM);
    const uint32_t* gm = reinterpret_cast<const uint32_t*>(g_Mbf) + cbase*32;
    for (int i = tid; i < 128*32; i += 256) {
        int c = i >> 5, w = i & 31;
        sm32[c*36 + w] = gm[i];
    }
    if (tid < 128) { s_s[tid] = g_bns[cbase + tid]; s_t[tid] = g_bnt[cbase + tid]; }
    __syncthreads();

    int warp = tid >> 5, lane = tid & 31;
    int qr = lane >> 2, qc = lane & 3;
    int wm = warp & 3, wn = warp >> 2;
    int rowbase = mt*128 + wm*32;

    float acc[2][8][4];
    #pragma unroll
    for (int s = 0; s < 2; s++)
        #pragma unroll
        for (int nt = 0; nt < 8; nt++)
            #pragma unroll
            for (int r = 0; r < 4; r++) acc[s][nt][r] = 0.f;

    const uint32_t* lgb = g_logbf + ((size_t)(mt*4 + wm))*1024 + lane*4;

    #pragma unroll
    for (int t = 0; t < 4; t++) {
        int jj = t * 16;
        uint32_t a[2][4];
        #pragma unroll
        for (int s = 0; s < 2; s++) {
            uint4 v = *reinterpret_cast<const uint4*>(lgb + (t*2 + s)*128);
            a[s][0] = v.x; a[s][1] = v.y; a[s][2] = v.z; a[s][3] = v.w;
        }
        int bofs = (jj >> 1) + qc;
        #pragma unroll
        for (int nt = 0; nt < 8; nt++) {
            int cl = wn*64 + nt*8 + qr;
            uint32_t bb[2] = { sm32[cl*36 + bofs], sm32[cl*36 + bofs + 4] };
            mma16816(acc[0][nt], a[0], bb);
            mma16816(acc[1][nt], a[1], bb);
        }
    }

    // ---- epilogue: pair-shuffle adjacent qc lanes into float4 columns ----
    // qc even keeps nt=2p (receives neighbor's even-nt pair);
    // qc odd keeps nt=2p+1 (receives neighbor's odd-nt pair).
    int qce = qc & 1;
    #pragma unroll
    for (int p = 0; p < 4; p++) {
        int col4 = wn*64 + (2*p + qce)*8 + (qc & 2)*2;
        float4 s4 = *reinterpret_cast<const float4*>(&s_s[col4]);
        float4 t4 = *reinterpret_cast<const float4*>(&s_t[col4]);
        int col = cbase + col4;
        #pragma unroll
        for (int s = 0; s < 2; s++) {
            #pragma unroll
            for (int rh = 0; rh < 2; rh++) {
                float e0 = acc[s][2*p  ][rh*2], e1 = acc[s][2*p  ][rh*2+1];
                float o0 = acc[s][2*p+1][rh*2], o1 = acc[s][2*p+1][rh*2+1];
                float sx = qce ? e0 : o0;
                float sy = qce ? e1 : o1;
                float rx = __shfl_xor_sync(0xffffffffu, sx, 1);
                float ry = __shfl_xor_sync(0xffffffffu, sy, 1);
                float4 v;
                if (qce) { v.x = rx; v.y = ry; v.z = o0; v.w = o1; }
                else     { v.x = e0; v.y = e1; v.z = rx; v.w = ry; }
                int row = rowbase + qr + s*16 + rh*8;
                float4 r4 = *reinterpret_cast<const float4*>(&in[(size_t)row*CDIM + col]);
                float4 o;
                o.x = fmaxf(fmaf(v.x, s4.x, t4.x) + r4.x, 0.f);
                o.y = fmaxf(fmaf(v.y, s4.y, t4.y) + r4.y, 0.f);
                o.z = fmaxf(fmaf(v.z, s4.z, t4.z) + r4.z, 0.f);
                o.w = fmaxf(fmaf(v.w, s4.w, t4.w) + r4.w, 0.f);
                *reinterpret_cast<float4*>(&out[(size_t)row*CDIM + col]) = o;
            }
        }
    }
}

// ---------- launch ----------
extern "C" void kernel_launch(void* const* d_in, const int* in_sizes, int n_in,
                              void* d_out, int out_size) {
    (void)in_sizes; (void)n_in; (void)out_size;
    const float* inputs = (const float*)d_in[0];
    const float* w1     = (const float*)d_in[1];
    const float* b1     = (const float*)d_in[2];
    const float* m0     = (const float*)d_in[3];
    const float* m1     = (const float*)d_in[4];
    const float* w2     = (const float*)d_in[5];
    const float* gamma  = (const float*)d_in[6];
    const float* beta   = (const float*)d_in[7];
    const float* bmean  = (const float*)d_in[8];
    const float* bvar   = (const float*)d_in[9];

    cudaFuncSetAttribute(kl_f4, cudaFuncAttributeMaxDynamicSharedMemorySize,
                         SMEM_LOGITS);

    kf_fold<<<1026, 256>>>(w1, b1, m0, m1, w2, gamma, beta, bmean, bvar);
    kl_f4<<<NCHUNK, 256, SMEM_LOGITS>>>(inputs);
    kp_norm<<<256, 256>>>();
    ko_pmm<<<dim3(ROWS / 128, 4), 256>>>(inputs, (float*)d_out);
}

// round 15
// speedup vs baseline: 1.2110x; 1.0937x over previous
#include <cuda_runtime.h>
#include <cuda_bf16.h>
#include <cstdint>

#define BATCH 16
#define NTOK  4096
#define CDIM  512
#define JDIM  64
#define ROWS  (BATCH*NTOK)   // 65536
#define NCHUNK 256           // 256-row softmax chunks (16 per batch)

// ---------- scratch (device globals; no runtime allocation) ----------
__device__ __nv_bfloat16 g_Wbf[JDIM*CDIM];   // fused w1@m0, [j][c]
__device__ float         g_blog[JDIM];       // b1@m0
__device__ __nv_bfloat16 g_Mbf[CDIM*JDIM];   // fused m1@w2, [c][j]
__device__ float         g_bns[CDIM], g_bnt[CDIM];
// logits (then probabilities), bf16, CHUNK-MAJOR fragment order:
//   [row/32 block][chunk 0..7][lane 0..31][4 u32]
__device__ uint32_t      g_logbf[2048*8*32*4];           // 8 MiB
__device__ float         g_pmax[NCHUNK*JDIM], g_psum[NCHUNK*JDIM];

// ---------- helpers ----------
__device__ __forceinline__ uint32_t packbf(float x, float y) {
    __nv_bfloat162 h = __floats2bfloat162_rn(x, y);
    return *reinterpret_cast<uint32_t*>(&h);
}
__device__ __forceinline__ float2 unpackbf(uint32_t u) {
    return __bfloat1622float2(*reinterpret_cast<__nv_bfloat162*>(&u));
}
__device__ __forceinline__ float rt_bf(float x) {
    return __bfloat162float(__float2bfloat16_rn(x));
}
__device__ __forceinline__ void mma16816(float* c, const uint32_t* a, const uint32_t* b) {
    asm volatile(
        "mma.sync.aligned.m16n8k16.row.col.f32.bf16.bf16.f32 "
        "{%0,%1,%2,%3},{%4,%5,%6,%7},{%8,%9},{%0,%1,%2,%3};"
        : "+f"(c[0]), "+f"(c[1]), "+f"(c[2]), "+f"(c[3])
        : "r"(a[0]), "r"(a[1]), "r"(a[2]), "r"(a[3]), "r"(b[0]), "r"(b[1]));
}
__device__ __forceinline__ void cp_async16(uint32_t saddr, const void* gptr) {
    asm volatile("cp.async.cg.shared.global [%0], [%1], 16;" :: "r"(saddr), "l"(gptr));
}

// ---------- K0: fold weights, split-K 4x128, float4 row loads ----------
__global__ __launch_bounds__(256) void kf_fold(const float* __restrict__ w1, const float* __restrict__ b1,
                       const float* __restrict__ m0, const float* __restrict__ m1,
                       const float* __restrict__ w2, const float* __restrict__ gamma,
                       const float* __restrict__ beta, const float* __restrict__ bmean,
                       const float* __restrict__ bvar) {
    __shared__ float red[4][64];
    int blk = blockIdx.x, tid = threadIdx.x;
    int ks = tid >> 6, lx = tid & 63;

    if (blk < 512) {
        const float4* r4 = reinterpret_cast<const float4*>(w1 + (size_t)blk*CDIM + ks*128);
        const float* m0c = m0 + (size_t)(ks*128)*JDIM + lx;
        float a0=0.f, a1=0.f, a2=0.f, a3=0.f;
        #pragma unroll 8
        for (int q4 = 0; q4 < 32; q4++) {
            float4 w = r4[q4];
            int q = q4 * 4;
            a0 = fmaf(w.x, m0c[(q  )*JDIM], a0);
            a1 = fmaf(w.y, m0c[(q+1)*JDIM], a1);
            a2 = fmaf(w.z, m0c[(q+2)*JDIM], a2);
            a3 = fmaf(w.w, m0c[(q+3)*JDIM], a3);
        }
        red[ks][lx] = (a0 + a1) + (a2 + a3);
        __syncthreads();
        if (tid < 64)
            g_Wbf[tid*CDIM + blk] = __float2bfloat16_rn(
                (red[0][tid] + red[1][tid]) + (red[2][tid] + red[3][tid]));
    } else if (blk < 1024) {
        int i = blk - 512;
        int j = i >> 3, cb = i & 7;
        int c = cb*64 + lx;
        const float4* r4 = reinterpret_cast<const float4*>(m1 + (size_t)j*CDIM + ks*128);
        const float* w2c = w2 + (size_t)(ks*128)*CDIM + c;
        float a0=0.f, a1=0.f, a2=0.f, a3=0.f;
        #pragma unroll 8
        for (int q4 = 0; q4 < 32; q4++) {
            float4 m = r4[q4];
            int q = q4 * 4;
            a0 = fmaf(m.x, w2c[(q  )*CDIM], a0);
            a1 = fmaf(m.y, w2c[(q+1)*CDIM], a1);
            a2 = fmaf(m.z, w2c[(q+2)*CDIM], a2);
            a3 = fmaf(m.w, w2c[(q+3)*CDIM], a3);
        }
        red[ks][lx] = (a0 + a1) + (a2 + a3);
        __syncthreads();
        if (tid < 64)
            g_Mbf[(cb*64 + tid)*JDIM + j] = __float2bfloat16_rn(
                (red[0][tid] + red[1][tid]) + (red[2][tid] + red[3][tid]));
    } else if (blk == 1024) {
        for (int c = tid; c < CDIM; c += 256) {
            float s = gamma[c] * rsqrtf(bvar[c] + 1e-3f);
            g_bns[c] = s;
            g_bnt[c] = beta[c] - bmean[c] * s;
        }
    } else {
        const float4* r4 = reinterpret_cast<const float4*>(b1 + ks*128);
        const float* m0c = m0 + (size_t)(ks*128)*JDIM + lx;
        float a0=0.f, a1=0.f, a2=0.f, a3=0.f;
        #pragma unroll 8
        for (int q4 = 0; q4 < 32; q4++) {
            float4 w = r4[q4];
            int q = q4 * 4;
            a0 = fmaf(w.x, m0c[(q  )*JDIM], a0);
            a1 = fmaf(w.y, m0c[(q+1)*JDIM], a1);
            a2 = fmaf(w.z, m0c[(q+2)*JDIM], a2);
            a3 = fmaf(w.w, m0c[(q+3)*JDIM], a3);
        }
        red[ks][lx] = (a0 + a1) + (a2 + a3);
        __syncthreads();
        if (tid < 64)
            g_blog[tid] = (red[0][tid] + red[1][tid]) + (red[2][tid] + red[3][tid]);
    }
}

// ---------- K1: logits = inputs @ W + blog; float4 A loads; fused stats ----------
#define SMEM_LOGITS (64*260*4 + 64*4 + 8*64*4 + 64*4)   // 69120 B

__global__ __launch_bounds__(256) void kl_f4(const float* __restrict__ in) {
    extern __shared__ __align__(16) unsigned char dyn_smem[];
    uint32_t* sw32  = reinterpret_cast<uint32_t*>(dyn_smem);          // [64][260] u32
    float*    sblog = reinterpret_cast<float*>(dyn_smem + 64*260*4);  // [64]
    float*    s_red = sblog + 64;                                     // [8][64]
    float*    s_cmx = s_red + 8*64;                                   // [64]

    int tid = threadIdx.x;
    const uint32_t* gw = reinterpret_cast<const uint32_t*>(g_Wbf); // 256 words/row
    for (int i = tid; i < 64*256; i += 256) {
        int j = i >> 8, w = i & 255;
        sw32[j*260 + w] = gw[i];
    }
    if (tid < JDIM) sblog[tid] = g_blog[tid];
    __syncthreads();

    int warp = tid >> 5, lane = tid & 31;
    int qr = lane >> 2, qc = lane & 3;
    int rowbase = blockIdx.x * 256 + warp * 32;

    float acc[2][8][4];
    #pragma unroll
    for (int nt = 0; nt < 8; nt++) {
        float b0 = sblog[nt*8 + qc*2], b1v = sblog[nt*8 + qc*2 + 1];
        #pragma unroll
        for (int s = 0; s < 2; s++) {
            acc[s][nt][0] = b0; acc[s][nt][1] = b1v;
            acc[s][nt][2] = b0; acc[s][nt][3] = b1v;
        }
    }

    const float* abase = in + (size_t)(rowbase + qr) * CDIM + qc*4;

    #pragma unroll 2
    for (int kk = 0; kk < 512; kk += 16) {
        uint32_t a[2][4];
        #pragma unroll
        for (int s = 0; s < 2; s++) {
            const float* p = abase + s*16*CDIM + kk;
            float4 f0 = *reinterpret_cast<const float4*>(p);
            float4 f1 = *reinterpret_cast<const float4*>(p + 8*CDIM);
            a[s][0] = packbf(f0.x, f0.y);
            a[s][1] = packbf(f1.x, f1.y);
            a[s][2] = packbf(f0.z, f0.w);
            a[s][3] = packbf(f1.z, f1.w);
        }
        int bofs = (kk >> 1) + qc*2;
        #pragma unroll
        for (int nt = 0; nt < 8; nt++) {
            int n = nt*8 + qr;
            uint32_t b[2];
            b[0] = sw32[n*260 + bofs];
            b[1] = sw32[n*260 + bofs + 1];
            mma16816(acc[0][nt], a[0], b);
            mma16816(acc[1][nt], a[1], b);
        }
    }

    // ---- store logits, chunk-major: each STG is 512B contiguous per warp ----
    {
        uint32_t* dstbase = g_logbf + ((size_t)(blockIdx.x*8 + warp))*1024 + lane*4;
        #pragma unroll
        for (int t = 0; t < 4; t++)
            #pragma unroll
            for (int s = 0; s < 2; s++) {
                uint4 v;
                v.x = packbf(acc[s][2*t  ][0], acc[s][2*t  ][1]);
                v.y = packbf(acc[s][2*t  ][2], acc[s][2*t  ][3]);
                v.z = packbf(acc[s][2*t+1][0], acc[s][2*t+1][1]);
                v.w = packbf(acc[s][2*t+1][2], acc[s][2*t+1][3]);
                *reinterpret_cast<uint4*>(dstbase + (t*2 + s)*128) = v;
            }
    }

    // ---- fused softmax stats over this CTA's 256 rows (bf16-rounded) ----
    #pragma unroll
    for (int nt = 0; nt < 8; nt++) {
        #pragma unroll
        for (int h = 0; h < 2; h++) {
            float v = fmaxf(fmaxf(rt_bf(acc[0][nt][h]), rt_bf(acc[0][nt][h+2])),
                            fmaxf(rt_bf(acc[1][nt][h]), rt_bf(acc[1][nt][h+2])));
            v = fmaxf(v, __shfl_xor_sync(0xffffffffu, v, 4));
            v = fmaxf(v, __shfl_xor_sync(0xffffffffu, v, 8));
            v = fmaxf(v, __shfl_xor_sync(0xffffffffu, v, 16));
            if (lane < 4) s_red[warp*64 + nt*8 + qc*2 + h] = v;
        }
    }
    __syncthreads();
    if (tid < 64) {
        float m = s_red[tid];
        #pragma unroll
        for (int w = 1; w < 8; w++) m = fmaxf(m, s_red[w*64 + tid]);
        s_cmx[tid] = m;
    }
    __syncthreads();
    #pragma unroll
    for (int nt = 0; nt < 8; nt++) {
        #pragma unroll
        for (int h = 0; h < 2; h++) {
            float cm = s_cmx[nt*8 + qc*2 + h];
            float v = __expf(rt_bf(acc[0][nt][h]) - cm) + __expf(rt_bf(acc[0][nt][h+2]) - cm)
                    + __expf(rt_bf(acc[1][nt][h]) - cm) + __expf(rt_bf(acc[1][nt][h+2]) - cm);
            v += __shfl_xor_sync(0xffffffffu, v, 4);
            v += __shfl_xor_sync(0xffffffffu, v, 8);
            v += __shfl_xor_sync(0xffffffffu, v, 16);
            if (lane < 4) s_red[warp*64 + nt*8 + qc*2 + h] = v;
        }
    }
    __syncthreads();
    if (tid < 64) {
        float s = 0.f;
        #pragma unroll
        for (int w = 0; w < 8; w++) s += s_red[w*64 + tid];
        g_pmax[blockIdx.x*JDIM + tid] = s_cmx[tid];
        g_psum[blockIdx.x*JDIM + tid] = s;
    }
}

// ---------- K1b: logits -> probabilities in place (chunk-major) ----------
__global__ __launch_bounds__(256) void kp_norm() {
    __shared__ float s_tj[64];
    int tid = threadIdx.x, cta = blockIdx.x;
    int b = cta >> 4;
    if (tid < 64) {
        float pm[16];
        float gmx = -1e30f;
        #pragma unroll
        for (int ch = 0; ch < 16; ch++) {
            pm[ch] = g_pmax[(b*16 + ch)*JDIM + tid];
            gmx = fmaxf(gmx, pm[ch]);
        }
        float Z = 0.f;
        #pragma unroll
        for (int ch = 0; ch < 16; ch++)
            Z += g_psum[(b*16 + ch)*JDIM + tid] * __expf(pm[ch] - gmx);
        s_tj[tid] = -__logf(Z * (1.f + 1e-9f)) - gmx;
    }
    __syncthreads();

    int warp = tid >> 5, lane = tid & 31, qc = lane & 3;
    uint32_t* pb = g_logbf + ((size_t)(cta*8 + warp))*1024 + lane*4;

    #pragma unroll
    for (int k = 0; k < 8; k++) {
        int t = k >> 1;
        float tjA = s_tj[16*t + 2*qc],     tjB = s_tj[16*t + 2*qc + 1];
        float tjC = s_tj[16*t + 8 + 2*qc], tjD = s_tj[16*t + 8 + 2*qc + 1];
        uint4 v = *reinterpret_cast<const uint4*>(pb + k*128);
        float2 f;
        f = unpackbf(v.x); v.x = packbf(__expf(f.x + tjA), __expf(f.y + tjB));
        f = unpackbf(v.y); v.y = packbf(__expf(f.x + tjA), __expf(f.y + tjB));
        f = unpackbf(v.z); v.z = packbf(__expf(f.x + tjC), __expf(f.y + tjD));
        f = unpackbf(v.w); v.w = packbf(__expf(f.x + tjC), __expf(f.y + tjD));
        *reinterpret_cast<uint4*>(pb + k*128) = v;
    }
}

// ---------- K2: out = relu( BN( p @ M ) + inputs ) ----------
// 64x128 CTA tile, grid (1024,4). Residual staged via cp.async into smem at
// kernel entry so the MMA mainloop covers its DRAM latency; epilogue reads
// residual from smem (29cyc) and stores fire-and-forget.
#define KO_SRES_F   (64*132)                 // floats, 132 stride (pad)
#define KO_SM_OFF   (KO_SRES_F*4)            // 33792
#define KO_BNS_OFF  (KO_SM_OFF + 128*36*4)   // 52224
#define SMEM_KO     (KO_BNS_OFF + 128*4*2)   // 53248 B

__global__ __launch_bounds__(256, 4) void ko_pmm(const float* __restrict__ in,
                                                 float* __restrict__ out) {
    extern __shared__ __align__(16) unsigned char ko_smem[];
    float*    sRes = reinterpret_cast<float*>(ko_smem);                 // [64][132]
    uint32_t* sm32 = reinterpret_cast<uint32_t*>(ko_smem + KO_SM_OFF); // [128][36]
    float*    s_s  = reinterpret_cast<float*>(ko_smem + KO_BNS_OFF);   // [128]
    float*    s_t  = s_s + 128;                                        // [128]

    int tid = threadIdx.x;
    int mt = blockIdx.x, nt4 = blockIdx.y;
    int cbase = nt4 * 128;

    // 1. kick off residual staging: 64 rows x 128 cols fp32 (32KB)
    {
        const float* gsrc = in + (size_t)(mt*64)*CDIM + cbase;
        #pragma unroll
        for (int k = 0; k < 8; k++) {
            int seg = tid + k*256;           // 0..2047
            int row = seg >> 5, sc = seg & 31;
            uint32_t saddr = (uint32_t)__cvta_generic_to_shared(
                &sRes[row*132 + sc*4]);
            cp_async16(saddr, gsrc + (size_t)row*CDIM + sc*4);
        }
        asm volatile("cp.async.commit_group;" ::: "memory");
    }

    // 2. stage M tile + BN constants
    const uint32_t* gm = reinterpret_cast<const uint32_t*>(g_Mbf) + cbase*32;
    for (int i = tid; i < 128*32; i += 256) {
        int c = i >> 5, w = i & 31;
        sm32[c*36 + w] = gm[i];
    }
    if (tid < 128) { s_s[tid] = g_bns[cbase + tid]; s_t[tid] = g_bnt[cbase + tid]; }
    __syncthreads();

    int warp = tid >> 5, lane = tid & 31;
    int qr = lane >> 2, qc = lane & 3;
    int wm = warp & 1, wn = warp >> 1;       // 2 row strips x 4 col strips

    float acc[2][4][4];
    #pragma unroll
    for (int s = 0; s < 2; s++)
        #pragma unroll
        for (int nt = 0; nt < 4; nt++)
            #pragma unroll
            for (int r = 0; r < 4; r++) acc[s][nt][r] = 0.f;

    const uint32_t* lgb = g_logbf + ((size_t)(mt*2 + wm))*1024 + lane*4;

    #pragma unroll
    for (int t = 0; t < 4; t++) {
        uint32_t a[2][4];
        #pragma unroll
        for (int s = 0; s < 2; s++) {
            uint4 v = *reinterpret_cast<const uint4*>(lgb + (t*2 + s)*128);
            a[s][0] = v.x; a[s][1] = v.y; a[s][2] = v.z; a[s][3] = v.w;
        }
        int bofs = t*8 + qc;
        #pragma unroll
        for (int nt = 0; nt < 4; nt++) {
            int cl = wn*32 + nt*8 + qr;
            uint32_t bb[2] = { sm32[cl*36 + bofs], sm32[cl*36 + bofs + 4] };
            mma16816(acc[0][nt], a[0], bb);
            mma16816(acc[1][nt], a[1], bb);
        }
    }

    // 3. residual must be in smem now (mainloop covered the latency)
    asm volatile("cp.async.wait_group 0;" ::: "memory");
    __syncthreads();

    // 4. epilogue: pair-shuffle adjacent qc lanes into float4 columns
    int qce = qc & 1;
    #pragma unroll
    for (int p = 0; p < 2; p++) {
        int col4 = wn*32 + (2*p + qce)*8 + (qc & 2)*2;
        float4 s4 = *reinterpret_cast<const float4*>(&s_s[col4]);
        float4 t4 = *reinterpret_cast<const float4*>(&s_t[col4]);
        int col = cbase + col4;
        #pragma unroll
        for (int s = 0; s < 2; s++) {
            #pragma unroll
            for (int rh = 0; rh < 2; rh++) {
                float e0 = acc[s][2*p  ][rh*2], e1 = acc[s][2*p  ][rh*2+1];
                float o0 = acc[s][2*p+1][rh*2], o1 = acc[s][2*p+1][rh*2+1];
                float sx = qce ? e0 : o0;
                float sy = qce ? e1 : o1;
                float rx = __shfl_xor_sync(0xffffffffu, sx, 1);
                float ry = __shfl_xor_sync(0xffffffffu, sy, 1);
                float4 v;
                if (qce) { v.x = rx; v.y = ry; v.z = o0; v.w = o1; }
                else     { v.x = e0; v.y = e1; v.z = rx; v.w = ry; }
                int rl = wm*32 + qr + s*16 + rh*8;          // local row 0..63
                float4 r4 = *reinterpret_cast<const float4*>(&sRes[rl*132 + col4]);
                float4 o;
                o.x = fmaxf(fmaf(v.x, s4.x, t4.x) + r4.x, 0.f);
                o.y = fmaxf(fmaf(v.y, s4.y, t4.y) + r4.y, 0.f);
                o.z = fmaxf(fmaf(v.z, s4.z, t4.z) + r4.z, 0.f);
                o.w = fmaxf(fmaf(v.w, s4.w, t4.w) + r4.w, 0.f);
                int row = mt*64 + rl;
                *reinterpret_cast<float4*>(&out[(size_t)row*CDIM + col]) = o;
            }
        }
    }
}

// ---------- launch ----------
extern "C" void kernel_launch(void* const* d_in, const int* in_sizes, int n_in,
                              void* d_out, int out_size) {
    (void)in_sizes; (void)n_in; (void)out_size;
    const float* inputs = (const float*)d_in[0];
    const float* w1     = (const float*)d_in[1];
    const float* b1     = (const float*)d_in[2];
    const float* m0     = (const float*)d_in[3];
    const float* m1     = (const float*)d_in[4];
    const float* w2     = (const float*)d_in[5];
    const float* gamma  = (const float*)d_in[6];
    const float* beta   = (const float*)d_in[7];
    const float* bmean  = (const float*)d_in[8];
    const float* bvar   = (const float*)d_in[9];

    cudaFuncSetAttribute(kl_f4, cudaFuncAttributeMaxDynamicSharedMemorySize,
                         SMEM_LOGITS);
    cudaFuncSetAttribute(ko_pmm, cudaFuncAttributeMaxDynamicSharedMemorySize,
                         SMEM_KO);

    kf_fold<<<1026, 256>>>(w1, b1, m0, m1, w2, gamma, beta, bmean, bvar);
    kl_f4<<<NCHUNK, 256, SMEM_LOGITS>>>(inputs);
    kp_norm<<<256, 256>>>();
    ko_pmm<<<dim3(ROWS / 64, 4), 256, SMEM_KO>>>(inputs, (float*)d_out);
}

// round 16
// speedup vs baseline: 1.4466x; 1.1945x over previous
#include <cuda_runtime.h>
#include <cuda_bf16.h>
#include <cstdint>

#define BATCH 16
#define NTOK  4096
#define CDIM  512
#define JDIM  64
#define ROWS  (BATCH*NTOK)   // 65536
#define NCHUNK 256           // 256-row softmax chunks (16 per batch)

// ---------- scratch (device globals; no runtime allocation) ----------
__device__ __nv_bfloat16 g_Wbf[JDIM*CDIM];   // fused w1@m0, [j][c]
__device__ float         g_blog[JDIM];       // b1@m0
__device__ __nv_bfloat16 g_Mbf[CDIM*JDIM];   // fused m1@w2, [c][j]
__device__ float         g_bns[CDIM], g_bnt[CDIM];
// logits (then probabilities), bf16, CHUNK-MAJOR fragment order:
//   [row/32 block][chunk 0..7][lane 0..31][4 u32]
__device__ uint32_t      g_logbf[2048*8*32*4];           // 8 MiB
__device__ float         g_pmax[NCHUNK*JDIM], g_psum[NCHUNK*JDIM];

// ---------- helpers ----------
__device__ __forceinline__ uint32_t packbf(float x, float y) {
    __nv_bfloat162 h = __floats2bfloat162_rn(x, y);
    return *reinterpret_cast<uint32_t*>(&h);
}
__device__ __forceinline__ float2 unpackbf(uint32_t u) {
    return __bfloat1622float2(*reinterpret_cast<__nv_bfloat162*>(&u));
}
__device__ __forceinline__ float rt_bf(float x) {
    return __bfloat162float(__float2bfloat16_rn(x));
}
__device__ __forceinline__ void mma16816(float* c, const uint32_t* a, const uint32_t* b) {
    asm volatile(
        "mma.sync.aligned.m16n8k16.row.col.f32.bf16.bf16.f32 "
        "{%0,%1,%2,%3},{%4,%5,%6,%7},{%8,%9},{%0,%1,%2,%3};"
        : "+f"(c[0]), "+f"(c[1]), "+f"(c[2]), "+f"(c[3])
        : "r"(a[0]), "r"(a[1]), "r"(a[2]), "r"(a[3]), "r"(b[0]), "r"(b[1]));
}
__device__ __forceinline__ void cp_async16(uint32_t saddr, const void* gptr) {
    asm volatile("cp.async.cg.shared.global [%0], [%1], 16;" :: "r"(saddr), "l"(gptr));
}

// ---------- K0: fold weights, split-K 4x128, float4 row loads ----------
__global__ __launch_bounds__(256) void kf_fold(const float* __restrict__ w1, const float* __restrict__ b1,
                       const float* __restrict__ m0, const float* __restrict__ m1,
                       const float* __restrict__ w2, const float* __restrict__ gamma,
                       const float* __restrict__ beta, const float* __restrict__ bmean,
                       const float* __restrict__ bvar) {
    __shared__ float red[4][64];
    int blk = blockIdx.x, tid = threadIdx.x;
    int ks = tid >> 6, lx = tid & 63;

    if (blk < 512) {
        const float4* r4 = reinterpret_cast<const float4*>(w1 + (size_t)blk*CDIM + ks*128);
        const float* m0c = m0 + (size_t)(ks*128)*JDIM + lx;
        float a0=0.f, a1=0.f, a2=0.f, a3=0.f;
        #pragma unroll 8
        for (int q4 = 0; q4 < 32; q4++) {
            float4 w = r4[q4];
            int q = q4 * 4;
            a0 = fmaf(w.x, m0c[(q  )*JDIM], a0);
            a1 = fmaf(w.y, m0c[(q+1)*JDIM], a1);
            a2 = fmaf(w.z, m0c[(q+2)*JDIM], a2);
            a3 = fmaf(w.w, m0c[(q+3)*JDIM], a3);
        }
        red[ks][lx] = (a0 + a1) + (a2 + a3);
        __syncthreads();
        if (tid < 64)
            g_Wbf[tid*CDIM + blk] = __float2bfloat16_rn(
                (red[0][tid] + red[1][tid]) + (red[2][tid] + red[3][tid]));
    } else if (blk < 1024) {
        int i = blk - 512;
        int j = i >> 3, cb = i & 7;
        int c = cb*64 + lx;
        const float4* r4 = reinterpret_cast<const float4*>(m1 + (size_t)j*CDIM + ks*128);
        const float* w2c = w2 + (size_t)(ks*128)*CDIM + c;
        float a0=0.f, a1=0.f, a2=0.f, a3=0.f;
        #pragma unroll 8
        for (int q4 = 0; q4 < 32; q4++) {
            float4 m = r4[q4];
            int q = q4 * 4;
            a0 = fmaf(m.x, w2c[(q  )*CDIM], a0);
            a1 = fmaf(m.y, w2c[(q+1)*CDIM], a1);
            a2 = fmaf(m.z, w2c[(q+2)*CDIM], a2);
            a3 = fmaf(m.w, w2c[(q+3)*CDIM], a3);
        }
        red[ks][lx] = (a0 + a1) + (a2 + a3);
        __syncthreads();
        if (tid < 64)
            g_Mbf[(cb*64 + tid)*JDIM + j] = __float2bfloat16_rn(
                (red[0][tid] + red[1][tid]) + (red[2][tid] + red[3][tid]));
    } else if (blk == 1024) {
        for (int c = tid; c < CDIM; c += 256) {
            float s = gamma[c] * rsqrtf(bvar[c] + 1e-3f);
            g_bns[c] = s;
            g_bnt[c] = beta[c] - bmean[c] * s;
        }
    } else {
        const float4* r4 = reinterpret_cast<const float4*>(b1 + ks*128);
        const float* m0c = m0 + (size_t)(ks*128)*JDIM + lx;
        float a0=0.f, a1=0.f, a2=0.f, a3=0.f;
        #pragma unroll 8
        for (int q4 = 0; q4 < 32; q4++) {
            float4 w = r4[q4];
            int q = q4 * 4;
            a0 = fmaf(w.x, m0c[(q  )*JDIM], a0);
            a1 = fmaf(w.y, m0c[(q+1)*JDIM], a1);
            a2 = fmaf(w.z, m0c[(q+2)*JDIM], a2);
            a3 = fmaf(w.w, m0c[(q+3)*JDIM], a3);
        }
        red[ks][lx] = (a0 + a1) + (a2 + a3);
        __syncthreads();
        if (tid < 64)
            g_blog[tid] = (red[0][tid] + red[1][tid]) + (red[2][tid] + red[3][tid]);
    }
}

// ---------- K1: logits = inputs @ W + blog; float4 A loads; fused stats ----------
#define SMEM_LOGITS (64*260*4 + 64*4 + 8*64*4 + 64*4)   // 69120 B

__global__ __launch_bounds__(256) void kl_f4(const float* __restrict__ in) {
    extern __shared__ __align__(16) unsigned char dyn_smem[];
    uint32_t* sw32  = reinterpret_cast<uint32_t*>(dyn_smem);          // [64][260] u32
    float*    sblog = reinterpret_cast<float*>(dyn_smem + 64*260*4);  // [64]
    float*    s_red = sblog + 64;                                     // [8][64]
    float*    s_cmx = s_red + 8*64;                                   // [64]

    int tid = threadIdx.x;
    const uint32_t* gw = reinterpret_cast<const uint32_t*>(g_Wbf); // 256 words/row
    for (int i = tid; i < 64*256; i += 256) {
        int j = i >> 8, w = i & 255;
        sw32[j*260 + w] = gw[i];
    }
    if (tid < JDIM) sblog[tid] = g_blog[tid];
    __syncthreads();

    int warp = tid >> 5, lane = tid & 31;
    int qr = lane >> 2, qc = lane & 3;
    int rowbase = blockIdx.x * 256 + warp * 32;

    float acc[2][8][4];
    #pragma unroll
    for (int nt = 0; nt < 8; nt++) {
        float b0 = sblog[nt*8 + qc*2], b1v = sblog[nt*8 + qc*2 + 1];
        #pragma unroll
        for (int s = 0; s < 2; s++) {
            acc[s][nt][0] = b0; acc[s][nt][1] = b1v;
            acc[s][nt][2] = b0; acc[s][nt][3] = b1v;
        }
    }

    const float* abase = in + (size_t)(rowbase + qr) * CDIM + qc*4;

    #pragma unroll 2
    for (int kk = 0; kk < 512; kk += 16) {
        uint32_t a[2][4];
        #pragma unroll
        for (int s = 0; s < 2; s++) {
            const float* p = abase + s*16*CDIM + kk;
            float4 f0 = *reinterpret_cast<const float4*>(p);
            float4 f1 = *reinterpret_cast<const float4*>(p + 8*CDIM);
            a[s][0] = packbf(f0.x, f0.y);
            a[s][1] = packbf(f1.x, f1.y);
            a[s][2] = packbf(f0.z, f0.w);
            a[s][3] = packbf(f1.z, f1.w);
        }
        int bofs = (kk >> 1) + qc*2;
        #pragma unroll
        for (int nt = 0; nt < 8; nt++) {
            int n = nt*8 + qr;
            uint32_t b[2];
            b[0] = sw32[n*260 + bofs];
            b[1] = sw32[n*260 + bofs + 1];
            mma16816(acc[0][nt], a[0], b);
            mma16816(acc[1][nt], a[1], b);
        }
    }

    // ---- store logits, chunk-major: each STG is 512B contiguous per warp ----
    {
        uint32_t* dstbase = g_logbf + ((size_t)(blockIdx.x*8 + warp))*1024 + lane*4;
        #pragma unroll
        for (int t = 0; t < 4; t++)
            #pragma unroll
            for (int s = 0; s < 2; s++) {
                uint4 v;
                v.x = packbf(acc[s][2*t  ][0], acc[s][2*t  ][1]);
                v.y = packbf(acc[s][2*t  ][2], acc[s][2*t  ][3]);
                v.z = packbf(acc[s][2*t+1][0], acc[s][2*t+1][1]);
                v.w = packbf(acc[s][2*t+1][2], acc[s][2*t+1][3]);
                *reinterpret_cast<uint4*>(dstbase + (t*2 + s)*128) = v;
            }
    }

    // ---- fused softmax stats over this CTA's 256 rows (bf16-rounded) ----
    #pragma unroll
    for (int nt = 0; nt < 8; nt++) {
        #pragma unroll
        for (int h = 0; h < 2; h++) {
            float v = fmaxf(fmaxf(rt_bf(acc[0][nt][h]), rt_bf(acc[0][nt][h+2])),
                            fmaxf(rt_bf(acc[1][nt][h]), rt_bf(acc[1][nt][h+2])));
            v = fmaxf(v, __shfl_xor_sync(0xffffffffu, v, 4));
            v = fmaxf(v, __shfl_xor_sync(0xffffffffu, v, 8));
            v = fmaxf(v, __shfl_xor_sync(0xffffffffu, v, 16));
            if (lane < 4) s_red[warp*64 + nt*8 + qc*2 + h] = v;
        }
    }
    __syncthreads();
    if (tid < 64) {
        float m = s_red[tid];
        #pragma unroll
        for (int w = 1; w < 8; w++) m = fmaxf(m, s_red[w*64 + tid]);
        s_cmx[tid] = m;
    }
    __syncthreads();
    #pragma unroll
    for (int nt = 0; nt < 8; nt++) {
        #pragma unroll
        for (int h = 0; h < 2; h++) {
            float cm = s_cmx[nt*8 + qc*2 + h];
            float v = __expf(rt_bf(acc[0][nt][h]) - cm) + __expf(rt_bf(acc[0][nt][h+2]) - cm)
                    + __expf(rt_bf(acc[1][nt][h]) - cm) + __expf(rt_bf(acc[1][nt][h+2]) - cm);
            v += __shfl_xor_sync(0xffffffffu, v, 4);
            v += __shfl_xor_sync(0xffffffffu, v, 8);
            v += __shfl_xor_sync(0xffffffffu, v, 16);
            if (lane < 4) s_red[warp*64 + nt*8 + qc*2 + h] = v;
        }
    }
    __syncthreads();
    if (tid < 64) {
        float s = 0.f;
        #pragma unroll
        for (int w = 0; w < 8; w++) s += s_red[w*64 + tid];
        g_pmax[blockIdx.x*JDIM + tid] = s_cmx[tid];
        g_psum[blockIdx.x*JDIM + tid] = s;
    }
}

// ---------- K1b: logits -> probabilities in place (chunk-major) ----------
__global__ __launch_bounds__(256) void kp_norm() {
    __shared__ float s_tj[64];
    int tid = threadIdx.x, cta = blockIdx.x;
    int b = cta >> 4;
    if (tid < 64) {
        float pm[16];
        float gmx = -1e30f;
        #pragma unroll
        for (int ch = 0; ch < 16; ch++) {
            pm[ch] = g_pmax[(b*16 + ch)*JDIM + tid];
            gmx = fmaxf(gmx, pm[ch]);
        }
        float Z = 0.f;
        #pragma unroll
        for (int ch = 0; ch < 16; ch++)
            Z += g_psum[(b*16 + ch)*JDIM + tid] * __expf(pm[ch] - gmx);
        s_tj[tid] = -__logf(Z * (1.f + 1e-9f)) - gmx;
    }
    __syncthreads();

    int warp = tid >> 5, lane = tid & 31, qc = lane & 3;
    uint32_t* pb = g_logbf + ((size_t)(cta*8 + warp))*1024 + lane*4;

    #pragma unroll
    for (int k = 0; k < 8; k++) {
        int t = k >> 1;
        float tjA = s_tj[16*t + 2*qc],     tjB = s_tj[16*t + 2*qc + 1];
        float tjC = s_tj[16*t + 8 + 2*qc], tjD = s_tj[16*t + 8 + 2*qc + 1];
        uint4 v = *reinterpret_cast<const uint4*>(pb + k*128);
        float2 f;
        f = unpackbf(v.x); v.x = packbf(__expf(f.x + tjA), __expf(f.y + tjB));
        f = unpackbf(v.y); v.y = packbf(__expf(f.x + tjA), __expf(f.y + tjB));
        f = unpackbf(v.z); v.z = packbf(__expf(f.x + tjC), __expf(f.y + tjD));
        f = unpackbf(v.w); v.w = packbf(__expf(f.x + tjC), __expf(f.y + tjD));
        *reinterpret_cast<uint4*>(pb + k*128) = v;
    }
}

// ---------- K2: out = relu( BN( p @ M ) + inputs ) — fully async-staged ----------
// 64x128 CTA tile, grid (1024,4). ALL inputs (residual, logits, M tile) staged
// via cp.async at entry in two groups; mainloop+epilogue read smem only.
#define KO_SRES_F   (64*132)                   // floats, stride 132
#define KO_LOG_OFF  (KO_SRES_F*4)              // 33792: logits 8KB (u32[2048])
#define KO_SM_OFF   (KO_LOG_OFF + 8192)        // 41984: M tile [128][36] u32
#define KO_BNS_OFF  (KO_SM_OFF + 128*36*4)     // 60416
#define SMEM_KO     (KO_BNS_OFF + 128*4*2)     // 61440 B

__global__ __launch_bounds__(256, 3) void ko_pmm(const float* __restrict__ in,
                                                 float* __restrict__ out) {
    extern __shared__ __align__(16) unsigned char ko_smem[];
    float*    sRes  = reinterpret_cast<float*>(ko_smem);                  // [64][132]
    uint32_t* sLog  = reinterpret_cast<uint32_t*>(ko_smem + KO_LOG_OFF);  // [2048]
    uint32_t* sm32  = reinterpret_cast<uint32_t*>(ko_smem + KO_SM_OFF);   // [128][36]
    float*    s_s   = reinterpret_cast<float*>(ko_smem + KO_BNS_OFF);     // [128]
    float*    s_t   = s_s + 128;                                          // [128]

    int tid = threadIdx.x;
    int mt = blockIdx.x, nt4 = blockIdx.y;
    int cbase = nt4 * 128;

    // ---- group A: M tile + logits (needed for mainloop) ----
    {
        const uint32_t* gm = reinterpret_cast<const uint32_t*>(g_Mbf) + cbase*32;
        #pragma unroll
        for (int k = 0; k < 4; k++) {
            int i = tid + k*256;            // 0..1023
            int c = i >> 3, ch = i & 7;     // row, 16B chunk
            uint32_t saddr = (uint32_t)__cvta_generic_to_shared(&sm32[c*36 + ch*4]);
            cp_async16(saddr, gm + c*32 + ch*4);
        }
        const uint32_t* gl = g_logbf + (size_t)(mt*2)*1024;
        #pragma unroll
        for (int k = 0; k < 2; k++) {
            int i = tid + k*256;            // 0..511
            uint32_t saddr = (uint32_t)__cvta_generic_to_shared(&sLog[i*4]);
            cp_async16(saddr, gl + i*4);
        }
        asm volatile("cp.async.commit_group;" ::: "memory");
    }
    // ---- group B: residual tile ----
    {
        const float* gsrc = in + (size_t)(mt*64)*CDIM + cbase;
        #pragma unroll
        for (int k = 0; k < 8; k++) {
            int seg = tid + k*256;           // 0..2047
            int row = seg >> 5, sc = seg & 31;
            uint32_t saddr = (uint32_t)__cvta_generic_to_shared(&sRes[row*132 + sc*4]);
            cp_async16(saddr, gsrc + (size_t)row*CDIM + sc*4);
        }
        asm volatile("cp.async.commit_group;" ::: "memory");
    }
    // BN constants (tiny, L2-hot)
    if (tid < 128) { s_s[tid] = g_bns[cbase + tid]; s_t[tid] = g_bnt[cbase + tid]; }

    // wait for group A (M + logits); group B may still be in flight
    asm volatile("cp.async.wait_group 1;" ::: "memory");
    __syncthreads();

    int warp = tid >> 5, lane = tid & 31;
    int qr = lane >> 2, qc = lane & 3;
    int wm = warp & 1, wn = warp >> 1;       // 2 row strips x 4 col strips

    float acc[2][4][4];
    #pragma unroll
    for (int s = 0; s < 2; s++)
        #pragma unroll
        for (int nt = 0; nt < 4; nt++)
            #pragma unroll
            for (int r = 0; r < 4; r++) acc[s][nt][r] = 0.f;

    const uint32_t* lgs = sLog + wm*1024 + lane*4;

    #pragma unroll
    for (int t = 0; t < 4; t++) {
        uint32_t a[2][4];
        #pragma unroll
        for (int s = 0; s < 2; s++) {
            uint4 v = *reinterpret_cast<const uint4*>(lgs + (t*2 + s)*128);
            a[s][0] = v.x; a[s][1] = v.y; a[s][2] = v.z; a[s][3] = v.w;
        }
        int bofs = t*8 + qc;
        #pragma unroll
        for (int nt = 0; nt < 4; nt++) {
            int cl = wn*32 + nt*8 + qr;
            uint32_t bb[2] = { sm32[cl*36 + bofs], sm32[cl*36 + bofs + 4] };
            mma16816(acc[0][nt], a[0], bb);
            mma16816(acc[1][nt], a[1], bb);
        }
    }

    // wait for group B (residual)
    asm volatile("cp.async.wait_group 0;" ::: "memory");
    __syncthreads();

    // epilogue: pair-shuffle adjacent qc lanes into float4 columns
    int qce = qc & 1;
    #pragma unroll
    for (int p = 0; p < 2; p++) {
        int col4 = wn*32 + (2*p + qce)*8 + (qc & 2)*2;
        float4 s4 = *reinterpret_cast<const float4*>(&s_s[col4]);
        float4 t4 = *reinterpret_cast<const float4*>(&s_t[col4]);
        int col = cbase + col4;
        #pragma unroll
        for (int s = 0; s < 2; s++) {
            #pragma unroll
            for (int rh = 0; rh < 2; rh++) {
                float e0 = acc[s][2*p  ][rh*2], e1 = acc[s][2*p  ][rh*2+1];
                float o0 = acc[s][2*p+1][rh*2], o1 = acc[s][2*p+1][rh*2+1];
                float sx = qce ? e0 : o0;
                float sy = qce ? e1 : o1;
                float rx = __shfl_xor_sync(0xffffffffu, sx, 1);
                float ry = __shfl_xor_sync(0xffffffffu, sy, 1);
                float4 v;
                if (qce) { v.x = rx; v.y = ry; v.z = o0; v.w = o1; }
                else     { v.x = e0; v.y = e1; v.z = rx; v.w = ry; }
                int rl = wm*32 + qr + s*16 + rh*8;          // local row 0..63
                float4 r4 = *reinterpret_cast<const float4*>(&sRes[rl*132 + col4]);
                float4 o;
                o.x = fmaxf(fmaf(v.x, s4.x, t4.x) + r4.x, 0.f);
                o.y = fmaxf(fmaf(v.y, s4.y, t4.y) + r4.y, 0.f);
                o.z = fmaxf(fmaf(v.z, s4.z, t4.z) + r4.z, 0.f);
                o.w = fmaxf(fmaf(v.w, s4.w, t4.w) + r4.w, 0.f);
                int row = mt*64 + rl;
                *reinterpret_cast<float4*>(&out[(size_t)row*CDIM + col]) = o;
            }
        }
    }
}

// ---------- launch ----------
extern "C" void kernel_launch(void* const* d_in, const int* in_sizes, int n_in,
                              void* d_out, int out_size) {
    (void)in_sizes; (void)n_in; (void)out_size;
    const float* inputs = (const float*)d_in[0];
    const float* w1     = (const float*)d_in[1];
    const float* b1     = (const float*)d_in[2];
    const float* m0     = (const float*)d_in[3];
    const float* m1     = (const float*)d_in[4];
    const float* w2     = (const float*)d_in[5];
    const float* gamma  = (const float*)d_in[6];
    const float* beta   = (const float*)d_in[7];
    const float* bmean  = (const float*)d_in[8];
    const float* bvar   = (const float*)d_in[9];

    cudaFuncSetAttribute(kl_f4, cudaFuncAttributeMaxDynamicSharedMemorySize,
                         SMEM_LOGITS);
    cudaFuncSetAttribute(ko_pmm, cudaFuncAttributeMaxDynamicSharedMemorySize,
                         SMEM_KO);

    kf_fold<<<1026, 256>>>(w1, b1, m0, m1, w2, gamma, beta, bmean, bvar);
    kl_f4<<<NCHUNK, 256, SMEM_LOGITS>>>(inputs);
    kp_norm<<<256, 256>>>();
    ko_pmm<<<dim3(ROWS / 64, 4), 256, SMEM_KO>>>(inputs, (float*)d_out);
}